// round 13
// baseline (speedup 1.0000x reference)
#include <cuda_runtime.h>
#include <cuda_bf16.h>
#include <cuda_fp16.h>
#include <cstdint>
#include <math.h>

// Problem constants
#define B_  2
#define L_  2048
#define NT  4096            // B*L tokens
#define D_  1024
#define H_  16
#define DH  64
#define D3  3072
#define EPS 1e-5f

// ---------------- scratch (device globals; no allocation) ----------------
__device__ __half g_hf[NT * D_];          // LN1 out (fp16)
__device__ __half g_wqf[D3 * D_];         // w_qkv (fp16)
__device__ __half g_owf[D_ * D_];         // out_w (fp16)
__device__ __half g_cf[NT * D_];          // ctx (fp16) [B,L,H,DH] == [NT,D]
__device__ __half g_qf[NT * D_];          // q (scaled, fp16) [BH,L,DH]
__device__ __half g_kf[NT * D_];          // k (fp16) [BH,L,DH]
__device__ __half g_vtf[NT * D_];         // v^T (fp16) [BH,DH,L]
__device__ float g_qkv[NT * D3];          // QKV gemm output [NT, 3D]
__device__ float g_cos[L_ * 32];
__device__ float g_sin[L_ * 32];

// ---------------- helpers ----------------
__device__ __forceinline__ uint32_t smem_u32(const void* p) {
    uint32_t a;
    asm("{ .reg .u64 t; cvta.to.shared.u64 t, %1; cvt.u32.u64 %0, t; }"
        : "=r"(a) : "l"(p));
    return a;
}
#define CP_ASYNC16(dst, src) \
    asm volatile("cp.async.cg.shared.global [%0], [%1], 16;" :: "r"(dst), "l"(src))
#define CP_COMMIT() asm volatile("cp.async.commit_group;" ::: "memory")
#define CP_WAIT0()  asm volatile("cp.async.wait_group 0;" ::: "memory")
#define CP_WAIT1()  asm volatile("cp.async.wait_group 1;" ::: "memory")

// fp16 mma
#define MMAF16(d, a, b) \
    asm volatile( \
        "mma.sync.aligned.m16n8k16.row.col.f32.f16.f16.f32 " \
        "{%0,%1,%2,%3}, {%4,%5,%6,%7}, {%8,%9}, {%0,%1,%2,%3};" \
        : "+f"((d)[0]), "+f"((d)[1]), "+f"((d)[2]), "+f"((d)[3]) \
        : "r"((a)[0]), "r"((a)[1]), "r"((a)[2]), "r"((a)[3]), \
          "r"((b)[0]), "r"((b)[1]))

// ---------------- fused prep: rope table + weight conv + LN1 ----------------
// grid: [0,256) rope | [256,3328) conv w_qkv | [3328,4352) conv out_w |
//       [4352,8448) ln1
__global__ void prep_kernel(const float* __restrict__ x,
                            const float* __restrict__ ln1w,
                            const float* __restrict__ ln1b,
                            const float* __restrict__ wq,
                            const float* __restrict__ ow) {
    int bid = blockIdx.x;
    int t = threadIdx.x;
    if (bid < 256) {
        int idx = bid * 256 + t;
        int l = idx >> 5;
        int j = idx & 31;
        float inv = powf(10000.0f, -(float)j / 32.0f);
        float ang = (float)l * inv;
        float s, c;
        sincosf(ang, &s, &c);
        g_cos[idx] = c;
        g_sin[idx] = s;
        return;
    }
    if (bid < 4352) {
        const float* src;
        __half* dst;
        int i;
        if (bid < 3328) { src = wq; dst = g_wqf; i = ((bid - 256) * 256 + t) * 4; }
        else            { src = ow; dst = g_owf; i = ((bid - 3328) * 256 + t) * 4; }
        float4 v = *(const float4*)&src[i];
        __half2 a = __floats2half2_rn(v.x, v.y);
        __half2 b = __floats2half2_rn(v.z, v.w);
        uint2 u;
        u.x = *(uint32_t*)&a;
        u.y = *(uint32_t*)&b;
        *(uint2*)&dst[i] = u;
        return;
    }
    // ---- ln1 ----
    int n = bid - 4352;
    const float* xr = x + (size_t)n * D_;
    float4 v = *(const float4*)&xr[t * 4];
    float s  = v.x + v.y + v.z + v.w;
    float s2 = v.x*v.x + v.y*v.y + v.z*v.z + v.w*v.w;
    #pragma unroll
    for (int o = 16; o >= 1; o >>= 1) {
        s  += __shfl_xor_sync(0xffffffffu, s,  o);
        s2 += __shfl_xor_sync(0xffffffffu, s2, o);
    }
    __shared__ float red[2][8];
    int lane = t & 31, wp = t >> 5;
    if (lane == 0) { red[0][wp] = s; red[1][wp] = s2; }
    __syncthreads();
    __shared__ float stat[2];
    if (t == 0) {
        float a = 0.f, c = 0.f;
        #pragma unroll
        for (int i = 0; i < 8; i++) { a += red[0][i]; c += red[1][i]; }
        float mu  = a * (1.0f / D_);
        float var = c * (1.0f / D_) - mu * mu;
        stat[0] = mu;
        stat[1] = rsqrtf(var + EPS);
    }
    __syncthreads();
    float mu = stat[0], rs = stat[1];
    float4 wv = *(const float4*)&ln1w[t * 4];
    float4 bv = *(const float4*)&ln1b[t * 4];
    float o0 = (v.x - mu) * rs * wv.x + bv.x;
    float o1 = (v.y - mu) * rs * wv.y + bv.y;
    float o2 = (v.z - mu) * rs * wv.z + bv.z;
    float o3 = (v.w - mu) * rs * wv.w + bv.w;
    __half2 a = __floats2half2_rn(o0, o1);
    __half2 bb = __floats2half2_rn(o2, o3);
    uint2 u;
    u.x = *(uint32_t*)&a;
    u.y = *(uint32_t*)&bb;
    *(uint2*)&g_hf[(size_t)n * D_ + t * 4] = u;
}

// ============ warp-MMA fp16 GEMM: C[M,N] = A[M,K]*B[N,K]^T (fp32 accum) ============
// CTA 128x128, 8 warps of 64x32. K64 pairs over 6-stage (3 pair-slot) ring.
#define GSUB   (128 * 16)                 // fp16 elems per K16 sub-buffer
#define GCH    (2 * GSUB)                 // elems per K32 chunk (4096)
#define GMAT   (6 * GCH)                  // elems per matrix (6 stages)
#define GEMM_SMEM_BYTES (2 * GMAT * 2)    // 98304 B

__global__ __launch_bounds__(256) void gemm_f16(
    const __half* __restrict__ Af, const __half* __restrict__ Bf,
    float* __restrict__ C, int M, int N, int K)
{
    extern __shared__ __half smg[];
    __half* sA = smg;
    __half* sB = smg + GMAT;

    int tid = threadIdx.x;
    int warp = tid >> 5, lane = tid & 31;
    int m0 = blockIdx.y * 128, n0 = blockIdx.x * 128;
    int wm = (warp & 1) * 64, wn = (warp >> 1) * 32;

    int lrow = tid >> 1;
    int lch  = (tid & 1) * 8;
    uint32_t uA = smem_u32(sA), uB = smem_u32(sB);
    uint32_t dsto = (uint32_t)(lrow * 16 + lch) * 2;    // within a sub buffer

    const __half* gA = Af + (size_t)(m0 + lrow) * K + lch;
    const __half* gB = Bf + (size_t)(n0 + lrow) * K + lch;

    float d[4][4][4];
    #pragma unroll
    for (int mi = 0; mi < 4; mi++)
        #pragma unroll
        for (int ni = 0; ni < 4; ni++)
            #pragma unroll
            for (int r = 0; r < 4; r++) d[mi][ni][r] = 0.f;

    const int npair = K >> 6;           // K64 pairs (K=1024 -> 16)

    #define CHUNK_OFF(c) ((uint32_t)((((c) >> 1) % 3) * 2 + ((c) & 1)) * GCH)

    // prologue: pairs 0,1 (chunks 0..3), one commit per pair
    #pragma unroll
    for (int c = 0; c < 4; c++) {
        #pragma unroll
        for (int sub = 0; sub < 2; sub++) {
            uint32_t so = (CHUNK_OFF(c) + (uint32_t)(sub * GSUB)) * 2 + dsto;
            CP_ASYNC16(uA + so, gA + c * 32 + sub * 16);
            CP_ASYNC16(uB + so, gB + c * 32 + sub * 16);
        }
        if (c & 1) CP_COMMIT();
    }

    int ar = wm + (lane >> 2);
    int ac = (lane & 3) * 2;
    int br = wn + (lane >> 2);
    int bc = (lane & 3) * 2;

    for (int p = 0; p < npair; p++) {
        if (p == npair - 1) { CP_WAIT0(); } else { CP_WAIT1(); }
        __syncthreads();

        if (p + 2 < npair) {
            #pragma unroll
            for (int ch = 0; ch < 2; ch++) {
                int c = 2 * (p + 2) + ch;
                #pragma unroll
                for (int sub = 0; sub < 2; sub++) {
                    uint32_t so = (CHUNK_OFF(c) + (uint32_t)(sub * GSUB)) * 2 + dsto;
                    CP_ASYNC16(uA + so, gA + c * 32 + sub * 16);
                    CP_ASYNC16(uB + so, gB + c * 32 + sub * 16);
                }
            }
        }
        CP_COMMIT();

        #pragma unroll
        for (int ch = 0; ch < 2; ch++) {
            int c = 2 * p + ch;
            #pragma unroll
            for (int sub = 0; sub < 2; sub++) {
                const __half* pA = sA + CHUNK_OFF(c) + sub * GSUB;
                const __half* pB = sB + CHUNK_OFF(c) + sub * GSUB;

                uint32_t ah[4][4], bh[4][2];
                #pragma unroll
                for (int mi = 0; mi < 4; mi++) {
                    int r0 = (ar + mi * 16) * 16 + ac;
                    int r1 = r0 + 8 * 16;
                    ah[mi][0] = *(const uint32_t*)(pA + r0);
                    ah[mi][1] = *(const uint32_t*)(pA + r1);
                    ah[mi][2] = *(const uint32_t*)(pA + r0 + 8);
                    ah[mi][3] = *(const uint32_t*)(pA + r1 + 8);
                }
                #pragma unroll
                for (int ni = 0; ni < 4; ni++) {
                    int c0 = (br + ni * 8) * 16 + bc;
                    bh[ni][0] = *(const uint32_t*)(pB + c0);
                    bh[ni][1] = *(const uint32_t*)(pB + c0 + 8);
                }

                #pragma unroll
                for (int mi = 0; mi < 4; mi++)
                    #pragma unroll
                    for (int ni = 0; ni < 4; ni++)
                        MMAF16(d[mi][ni], ah[mi], bh[ni]);
            }
        }
    }

    #pragma unroll
    for (int mi = 0; mi < 4; mi++) {
        int r = m0 + wm + mi * 16 + (lane >> 2);
        #pragma unroll
        for (int ni = 0; ni < 4; ni++) {
            int c = n0 + wn + ni * 8 + (lane & 3) * 2;
            *(float2*)&C[(size_t)r * N + c] = make_float2(d[mi][ni][0], d[mi][ni][1]);
            *(float2*)&C[(size_t)(r + 8) * N + c] = make_float2(d[mi][ni][2], d[mi][ni][3]);
        }
    }
}

// ---------- fused QK-LN+RoPE (blocks [0,4096)) + V transpose ([4096,6144)) ----------
__global__ void qkrope_vt_kernel(const float* __restrict__ qw,
                                 const float* __restrict__ kw) {
    int bid = blockIdx.x;
    int t = threadIdx.x;

    if (bid >= 4096) {
        // ---- V transpose: g_qkv v-part -> [BH,DH,L] fp16 ----
        __shared__ float tile[64][33];
        int bid2 = bid - 4096;
        int bh = bid2 >> 6;                 // 0..31
        int b = bh >> 4, h = bh & 15;
        int l0 = (bid2 & 63) * 32;
        int tx = t & 31, ty = t >> 5;
        #pragma unroll
        for (int i = 0; i < 4; i++) {
            int l = l0 + ty + i * 8;
            const float* row = g_qkv + (size_t)(b * L_ + l) * D3 + 2 * D_ + h * DH;
            tile[tx][ty + i * 8]      = row[tx];
            tile[tx + 32][ty + i * 8] = row[tx + 32];
        }
        __syncthreads();
        #pragma unroll
        for (int i = 0; i < 8; i++) {
            int d = ty + i * 8;
            size_t o = (size_t)(bh * DH + d) * L_ + l0 + tx;
            g_vtf[o] = __float2half_rn(tile[d][tx]);
        }
        return;
    }

    // ---- QK-LN + RoPE ----
    int n = bid;
    int b = n >> 11;
    int l = n & 2047;
    const float* q = g_qkv + (size_t)n * D3;
    const float* k = q + D_;

    float4 qv = *(const float4*)&q[t * 4];
    float4 kv = *(const float4*)&k[t * 4];
    float qs  = qv.x + qv.y + qv.z + qv.w;
    float qs2 = qv.x*qv.x + qv.y*qv.y + qv.z*qv.z + qv.w*qv.w;
    float ks  = kv.x + kv.y + kv.z + kv.w;
    float ks2 = kv.x*kv.x + kv.y*kv.y + kv.z*kv.z + kv.w*kv.w;
    #pragma unroll
    for (int o = 16; o >= 1; o >>= 1) {
        qs  += __shfl_xor_sync(0xffffffffu, qs,  o);
        qs2 += __shfl_xor_sync(0xffffffffu, qs2, o);
        ks  += __shfl_xor_sync(0xffffffffu, ks,  o);
        ks2 += __shfl_xor_sync(0xffffffffu, ks2, o);
    }
    __shared__ float red[4][8];
    __shared__ float stat[4];
    int lane = t & 31, wp = t >> 5;
    if (lane == 0) { red[0][wp]=qs; red[1][wp]=qs2; red[2][wp]=ks; red[3][wp]=ks2; }
    __syncthreads();
    if (t == 0) {
        float a=0,c=0,e=0,f=0;
        #pragma unroll
        for (int i=0;i<8;i++){a+=red[0][i];c+=red[1][i];e+=red[2][i];f+=red[3][i];}
        float qmu=a*(1.f/D_), qvr=c*(1.f/D_)-qmu*qmu;
        float kmu=e*(1.f/D_), kvr=f*(1.f/D_)-kmu*kmu;
        stat[0]=qmu; stat[1]=rsqrtf(qvr+EPS);
        stat[2]=kmu; stat[3]=rsqrtf(kvr+EPS);
    }
    __syncthreads();
    float qmu=stat[0], qrs=stat[1], kmu=stat[2], krs=stat[3];
    float4 qwv = *(const float4*)&qw[t*4];
    float4 kwv = *(const float4*)&kw[t*4];
    float qnv[4], knv[4];
    qnv[0]=(qv.x-qmu)*qrs*qwv.x; qnv[1]=(qv.y-qmu)*qrs*qwv.y;
    qnv[2]=(qv.z-qmu)*qrs*qwv.z; qnv[3]=(qv.w-qmu)*qrs*qwv.w;
    knv[0]=(kv.x-kmu)*krs*kwv.x; knv[1]=(kv.y-kmu)*krs*kwv.y;
    knv[2]=(kv.z-kmu)*krs*kwv.z; knv[3]=(kv.w-kmu)*krs*kwv.w;

    // RoPE partner (d +/- 32) lives exactly 8 lanes away in the same warp
    float qp[4], kp[4];
    #pragma unroll
    for (int ii = 0; ii < 4; ii++) {
        qp[ii] = __shfl_xor_sync(0xffffffffu, qnv[ii], 8);
        kp[ii] = __shfl_xor_sync(0xffffffffu, knv[ii], 8);
    }
    bool hiHalf = (t & 8) != 0;     // j0 >= 32
    int d0 = t * 4;
    int hh = d0 >> 6;
    int j0 = d0 & 63;
    int f0 = d0 & 31;
    float qo[4], ko[4];
    #pragma unroll
    for (int ii = 0; ii < 4; ii++) {
        float c = g_cos[l * 32 + f0 + ii];
        float s = g_sin[l * 32 + f0 + ii];
        if (!hiHalf) {
            qo[ii] = qnv[ii] * c - qp[ii] * s;
            ko[ii] = knv[ii] * c - kp[ii] * s;
        } else {
            qo[ii] = qnv[ii] * c + qp[ii] * s;
            ko[ii] = knv[ii] * c + kp[ii] * s;
        }
        qo[ii] *= 0.125f;   // fold softmax scale into q
    }
    size_t oidx = (((size_t)(b * H_ + hh)) * L_ + l) * DH + j0;
    __half2 q01 = __floats2half2_rn(qo[0], qo[1]);
    __half2 q23 = __floats2half2_rn(qo[2], qo[3]);
    __half2 k01 = __floats2half2_rn(ko[0], ko[1]);
    __half2 k23 = __floats2half2_rn(ko[2], ko[3]);
    uint2 uq, uk;
    uq.x = *(uint32_t*)&q01; uq.y = *(uint32_t*)&q23;
    uk.x = *(uint32_t*)&k01; uk.y = *(uint32_t*)&k23;
    *(uint2*)&g_qf[oidx] = uq;
    *(uint2*)&g_kf[oidx] = uk;
}

// ---------------- flash attention on mma.sync (fp16 single-term) ----------------
// Q staging smem ALIASES KV buffer 1: Q is register-resident before the first
// prefetch into that region. Layout: [0,18432) = KV buf1 (K,V) / Q staging;
// [18432,36864) = KV buf0; [36864,+512) = seq-id slots.
#define KPAD 72
#define A4_TILE 9216
#define A4_BUF  18432
#define A4_SK   36864
#define ATT4_SMEM (A4_SK + 512)

__global__ __launch_bounds__(128, 5) void attn_mma(const int* __restrict__ seq_id) {
    extern __shared__ char sm[];
    const uint32_t sbase = smem_u32(sm);
    int tid = threadIdx.x, lane = tid & 31, w = tid >> 5;
    int qt = blockIdx.x, h = blockIdx.y, b = blockIdx.z;
    int bh = b * H_ + h;
    int row0 = qt * 64;

    const __half* gQf = g_qf + ((size_t)bh * L_ + row0) * DH;
    const __half* gKf = g_kf + (size_t)bh * L_ * DH;
    const __half* gVf = g_vtf + (size_t)bh * DH * L_;

    // ---- valid k-tile range (contiguous because seq_id is sorted) ----
    int q_lo = seq_id[b * L_ + row0];
    int q_hi = seq_id[b * L_ + row0 + 63];
    unsigned vmask;
    {
        int klo = seq_id[b * L_ + lane * 64];
        int khi = seq_id[b * L_ + lane * 64 + 63];
        bool ok = (khi >= q_lo) && (klo <= q_hi);
        vmask = __ballot_sync(0xffffffffu, ok);
    }
    int tlo = __ffs(vmask) - 1;
    int thi = 31 - __clz(vmask);

    int lrow = tid >> 1;          // 0..63
    int cb0  = (tid & 1) * 4;     // chunk base (16B chunks)

    // ---- prologue: Q tile into buf1 region (offset 0) ----
    #pragma unroll
    for (int c = 0; c < 4; c++) {
        int ch = cb0 + c;
        uint32_t so = (uint32_t)(lrow * KPAD + ch * 8) * 2;
        CP_ASYNC16(sbase + so, gQf + lrow * DH + ch * 8);
    }
    CP_COMMIT();
    // ---- K/V tile tlo into buf0 region (offset A4_BUF) ----
    {
        int col0 = tlo * 64;
        uint32_t dst = sbase + A4_BUF;
        #pragma unroll
        for (int c = 0; c < 4; c++) {
            int ch = cb0 + c;
            uint32_t so = (uint32_t)(lrow * KPAD + ch * 8) * 2;
            CP_ASYNC16(dst + so,           gKf + (size_t)(col0 + lrow) * DH + ch * 8);
            CP_ASYNC16(dst + A4_TILE + so, gVf + (size_t)lrow * L_ + col0 + ch * 8);
        }
    }
    CP_COMMIT();
    if (tid < 64) ((int*)(sm + A4_SK))[tid] = seq_id[b * L_ + tlo * 64 + tid];
    int sq0 = seq_id[b * L_ + row0 + w * 16 + (lane >> 2)];
    int sq1 = seq_id[b * L_ + row0 + w * 16 + (lane >> 2) + 8];

    CP_WAIT1();                 // Q group complete (KV0 may be in flight)
    __syncthreads();

    // ---- extract Q fragments (held for whole kernel); frees buf1 region ----
    uint32_t qf[4][4];
    {
        const __half* sQ = (const __half*)sm;
        #pragma unroll
        for (int s = 0; s < 4; s++) {
            int base = (w * 16 + (lane >> 2)) * KPAD + s * 16 + (lane & 3) * 2;
            qf[s][0] = *(const uint32_t*)(sQ + base);
            qf[s][1] = *(const uint32_t*)(sQ + base + 8 * KPAD);
            qf[s][2] = *(const uint32_t*)(sQ + base + 8);
            qf[s][3] = *(const uint32_t*)(sQ + base + 8 * KPAD + 8);
        }
    }

    float m0 = -1e30f, m1 = -1e30f, l0 = 0.f, l1 = 0.f;
    float pv[8][4];
    #pragma unroll
    for (int j = 0; j < 8; j++)
        #pragma unroll
        for (int r = 0; r < 4; r++) pv[j][r] = 0.f;

    for (int it = tlo; it <= thi; it++) {
        int buf = (it - tlo) & 1;               // 0 -> region A4_BUF, 1 -> region 0
        uint32_t kvb  = sbase + (buf ? 0u : (uint32_t)A4_BUF);
        uint32_t kvbn = sbase + (buf ? (uint32_t)A4_BUF : 0u);
        CP_WAIT0();
        __syncthreads();                         // Q frags extracted by all warps

        // prefetch next tile into the other region (overwrites Q on first iter)
        if (it + 1 <= thi) {
            int col0n = (it + 1) * 64;
            #pragma unroll
            for (int c = 0; c < 4; c++) {
                int ch = cb0 + c;
                uint32_t so = (uint32_t)(lrow * KPAD + ch * 8) * 2;
                CP_ASYNC16(kvbn + so,           gKf + (size_t)(col0n + lrow) * DH + ch * 8);
                CP_ASYNC16(kvbn + A4_TILE + so, gVf + (size_t)lrow * L_ + col0n + ch * 8);
            }
            if (tid < 64)
                ((int*)(sm + A4_SK))[(buf ^ 1) * 64 + tid] =
                    seq_id[b * L_ + col0n + tid];
        }
        CP_COMMIT();

        const __half* sK = (const __half*)(sm + (kvb - sbase));
        const __half* sV = sK + A4_TILE / 2;
        const int* skp = (const int*)(sm + A4_SK) + buf * 64;

        // ---- S = Q K^T (fp16 single) ----
        float sf[8][4];
        #pragma unroll
        for (int j = 0; j < 8; j++)
            #pragma unroll
            for (int r = 0; r < 4; r++) sf[j][r] = 0.f;
        #pragma unroll
        for (int s = 0; s < 4; s++) {
            #pragma unroll
            for (int j = 0; j < 8; j++) {
                int off = (j * 8 + (lane >> 2)) * KPAD + s * 16 + (lane & 3) * 2;
                uint32_t bf[2] = {*(const uint32_t*)(sK + off),
                                  *(const uint32_t*)(sK + off + 8)};
                MMAF16(sf[j], qf[s], bf);
            }
        }

        // ---- mask + online softmax (c-frag layout) ----
        int colb = (lane & 3) * 2;
        float nm0 = m0, nm1 = m1;
        #pragma unroll
        for (int j = 0; j < 8; j++) {
            int k0 = skp[8 * j + colb], k1 = skp[8 * j + colb + 1];
            sf[j][0] = (k0 == sq0) ? sf[j][0] : -2e30f;
            sf[j][1] = (k1 == sq0) ? sf[j][1] : -2e30f;
            sf[j][2] = (k0 == sq1) ? sf[j][2] : -2e30f;
            sf[j][3] = (k1 == sq1) ? sf[j][3] : -2e30f;
            nm0 = fmaxf(nm0, fmaxf(sf[j][0], sf[j][1]));
            nm1 = fmaxf(nm1, fmaxf(sf[j][2], sf[j][3]));
        }
        nm0 = fmaxf(nm0, __shfl_xor_sync(0xffffffffu, nm0, 1));
        nm0 = fmaxf(nm0, __shfl_xor_sync(0xffffffffu, nm0, 2));
        nm1 = fmaxf(nm1, __shfl_xor_sync(0xffffffffu, nm1, 1));
        nm1 = fmaxf(nm1, __shfl_xor_sync(0xffffffffu, nm1, 2));
        float a0 = __expf(m0 - nm0), a1 = __expf(m1 - nm1);
        m0 = nm0; m1 = nm1;

        float s0 = 0.f, s1 = 0.f;
        uint32_t ph[4][4];
        #pragma unroll
        for (int j = 0; j < 8; j++) {
            float p0 = __expf(sf[j][0] - m0), p1 = __expf(sf[j][1] - m0);
            float p2 = __expf(sf[j][2] - m1), p3 = __expf(sf[j][3] - m1);
            s0 += p0 + p1; s1 += p2 + p3;
            __half2 h01 = __floats2half2_rn(p0, p1);
            __half2 h23 = __floats2half2_rn(p2, p3);
            int s_ = j >> 1;
            int o  = (j & 1) * 2;
            ph[s_][o]     = *(uint32_t*)&h01;
            ph[s_][o + 1] = *(uint32_t*)&h23;
        }
        s0 += __shfl_xor_sync(0xffffffffu, s0, 1);
        s0 += __shfl_xor_sync(0xffffffffu, s0, 2);
        s1 += __shfl_xor_sync(0xffffffffu, s1, 1);
        s1 += __shfl_xor_sync(0xffffffffu, s1, 2);
        l0 = l0 * a0 + s0;
        l1 = l1 * a1 + s1;
        #pragma unroll
        for (int j = 0; j < 8; j++) {
            pv[j][0] *= a0; pv[j][1] *= a0; pv[j][2] *= a1; pv[j][3] *= a1;
        }

        // ---- PV (fp16 single), B = Vt[dh][c] ----
        #pragma unroll
        for (int s = 0; s < 4; s++) {
            #pragma unroll
            for (int j = 0; j < 8; j++) {
                int off = (j * 8 + (lane >> 2)) * KPAD + s * 16 + (lane & 3) * 2;
                uint32_t bf[2] = {*(const uint32_t*)(sV + off),
                                  *(const uint32_t*)(sV + off + 8)};
                MMAF16(pv[j], ph[s], bf);
            }
        }
    }

    // ---- epilogue: ctx / l -> fp16 [B,L,H,DH] ----
    float inv0 = 1.0f / l0, inv1 = 1.0f / l1;
    int r0g = row0 + w * 16 + (lane >> 2);
    #pragma unroll
    for (int j = 0; j < 8; j++) {
        int c = 8 * j + (lane & 3) * 2;
        size_t o0 = (((size_t)b * L_ + r0g) * H_ + h) * DH + c;
        size_t o1 = (((size_t)b * L_ + r0g + 8) * H_ + h) * DH + c;
        __half2 hx = __floats2half2_rn(pv[j][0] * inv0, pv[j][1] * inv0);
        __half2 hy = __floats2half2_rn(pv[j][2] * inv1, pv[j][3] * inv1);
        *(uint32_t*)&g_cf[o0] = *(uint32_t*)&hx;
        *(uint32_t*)&g_cf[o1] = *(uint32_t*)&hy;
    }
}

// ---------------- launch ----------------
extern "C" void kernel_launch(void* const* d_in, const int* in_sizes, int n_in,
                              void* d_out, int out_size) {
    const float* x      = (const float*)d_in[0];
    const int*   seq_id = (const int*)  d_in[1];
    const float* ln1_w  = (const float*)d_in[2];
    const float* ln1_b  = (const float*)d_in[3];
    const float* w_qkv  = (const float*)d_in[4];
    const float* q_ln_w = (const float*)d_in[5];
    const float* k_ln_w = (const float*)d_in[6];
    const float* out_w  = (const float*)d_in[7];
    float* out = (float*)d_out;

    void *phf, *pwqf, *powf, *pcf, *pqkv;
    cudaGetSymbolAddress(&phf,  g_hf);
    cudaGetSymbolAddress(&pwqf, g_wqf);
    cudaGetSymbolAddress(&powf, g_owf);
    cudaGetSymbolAddress(&pcf,  g_cf);
    cudaGetSymbolAddress(&pqkv, g_qkv);

    cudaFuncSetAttribute(attn_mma, cudaFuncAttributeMaxDynamicSharedMemorySize,
                         ATT4_SMEM);
    cudaFuncSetAttribute(gemm_f16, cudaFuncAttributeMaxDynamicSharedMemorySize,
                         GEMM_SMEM_BYTES);

    prep_kernel<<<8448, 256>>>(x, ln1_w, ln1_b, w_qkv, out_w);
    gemm_f16<<<dim3(D3 / 128, NT / 128), 256, GEMM_SMEM_BYTES>>>(
        (const __half*)phf, (const __half*)pwqf, (float*)pqkv, NT, D3, D_);
    qkrope_vt_kernel<<<6144, 256>>>(q_ln_w, k_ln_w);
    attn_mma<<<dim3(L_ / 64, H_, B_), 128, ATT4_SMEM>>>(seq_id);
    gemm_f16<<<dim3(D_ / 128, NT / 128), 256, GEMM_SMEM_BYTES>>>(
        (const __half*)pcf, (const __half*)powf, out, NT, D_, D_);
}

// round 14
// speedup vs baseline: 1.0162x; 1.0162x over previous
#include <cuda_runtime.h>
#include <cuda_bf16.h>
#include <cuda_fp16.h>
#include <cstdint>
#include <math.h>

// Problem constants
#define B_  2
#define L_  2048
#define NT  4096            // B*L tokens
#define D_  1024
#define H_  16
#define DH  64
#define D3  3072
#define EPS 1e-5f

// ---------------- scratch (device globals; no allocation) ----------------
__device__ __half g_hf[NT * D_];          // LN1 out (fp16)
__device__ __half g_wqf[D3 * D_];         // w_qkv (fp16)
__device__ __half g_owf[D_ * D_];         // out_w (fp16)
__device__ __half g_cf[NT * D_];          // ctx (fp16) [B,L,H,DH] == [NT,D]
__device__ __half g_qf[NT * D_];          // q (scaled, fp16) [BH,L,DH]
__device__ __half g_kf[NT * D_];          // k (fp16) [BH,L,DH]
__device__ __half g_vtf[NT * D_];         // v^T (fp16) [BH,DH,L]
__device__ float g_qkv[NT * D3];          // QKV gemm output [NT, 3D]
__device__ float g_cos[L_ * 32];
__device__ float g_sin[L_ * 32];

// ---------------- helpers ----------------
__device__ __forceinline__ uint32_t smem_u32(const void* p) {
    uint32_t a;
    asm("{ .reg .u64 t; cvta.to.shared.u64 t, %1; cvt.u32.u64 %0, t; }"
        : "=r"(a) : "l"(p));
    return a;
}
#define CP_ASYNC16(dst, src) \
    asm volatile("cp.async.cg.shared.global [%0], [%1], 16;" :: "r"(dst), "l"(src))
#define CP_COMMIT() asm volatile("cp.async.commit_group;" ::: "memory")
#define CP_WAIT0()  asm volatile("cp.async.wait_group 0;" ::: "memory")
#define CP_WAIT1()  asm volatile("cp.async.wait_group 1;" ::: "memory")

// fp16 mma
#define MMAF16(d, a, b) \
    asm volatile( \
        "mma.sync.aligned.m16n8k16.row.col.f32.f16.f16.f32 " \
        "{%0,%1,%2,%3}, {%4,%5,%6,%7}, {%8,%9}, {%0,%1,%2,%3};" \
        : "+f"((d)[0]), "+f"((d)[1]), "+f"((d)[2]), "+f"((d)[3]) \
        : "r"((a)[0]), "r"((a)[1]), "r"((a)[2]), "r"((a)[3]), \
          "r"((b)[0]), "r"((b)[1]))

// ---------------- fused prep: rope table + weight conv + LN1 ----------------
// grid: [0,256) rope | [256,3328) conv w_qkv | [3328,4352) conv out_w |
//       [4352,8448) ln1
__global__ void prep_kernel(const float* __restrict__ x,
                            const float* __restrict__ ln1w,
                            const float* __restrict__ ln1b,
                            const float* __restrict__ wq,
                            const float* __restrict__ ow) {
    int bid = blockIdx.x;
    int t = threadIdx.x;
    if (bid < 256) {
        int idx = bid * 256 + t;
        int l = idx >> 5;
        int j = idx & 31;
        float inv = powf(10000.0f, -(float)j / 32.0f);
        float ang = (float)l * inv;
        float s, c;
        sincosf(ang, &s, &c);
        g_cos[idx] = c;
        g_sin[idx] = s;
        return;
    }
    if (bid < 4352) {
        const float* src;
        __half* dst;
        int i;
        if (bid < 3328) { src = wq; dst = g_wqf; i = ((bid - 256) * 256 + t) * 4; }
        else            { src = ow; dst = g_owf; i = ((bid - 3328) * 256 + t) * 4; }
        float4 v = *(const float4*)&src[i];
        __half2 a = __floats2half2_rn(v.x, v.y);
        __half2 b = __floats2half2_rn(v.z, v.w);
        uint2 u;
        u.x = *(uint32_t*)&a;
        u.y = *(uint32_t*)&b;
        *(uint2*)&dst[i] = u;
        return;
    }
    // ---- ln1 ----
    int n = bid - 4352;
    const float* xr = x + (size_t)n * D_;
    float4 v = *(const float4*)&xr[t * 4];
    float s  = v.x + v.y + v.z + v.w;
    float s2 = v.x*v.x + v.y*v.y + v.z*v.z + v.w*v.w;
    #pragma unroll
    for (int o = 16; o >= 1; o >>= 1) {
        s  += __shfl_xor_sync(0xffffffffu, s,  o);
        s2 += __shfl_xor_sync(0xffffffffu, s2, o);
    }
    __shared__ float red[2][8];
    int lane = t & 31, wp = t >> 5;
    if (lane == 0) { red[0][wp] = s; red[1][wp] = s2; }
    __syncthreads();
    __shared__ float stat[2];
    if (t == 0) {
        float a = 0.f, c = 0.f;
        #pragma unroll
        for (int i = 0; i < 8; i++) { a += red[0][i]; c += red[1][i]; }
        float mu  = a * (1.0f / D_);
        float var = c * (1.0f / D_) - mu * mu;
        stat[0] = mu;
        stat[1] = rsqrtf(var + EPS);
    }
    __syncthreads();
    float mu = stat[0], rs = stat[1];
    float4 wv = *(const float4*)&ln1w[t * 4];
    float4 bv = *(const float4*)&ln1b[t * 4];
    float o0 = (v.x - mu) * rs * wv.x + bv.x;
    float o1 = (v.y - mu) * rs * wv.y + bv.y;
    float o2 = (v.z - mu) * rs * wv.z + bv.z;
    float o3 = (v.w - mu) * rs * wv.w + bv.w;
    __half2 a = __floats2half2_rn(o0, o1);
    __half2 bb = __floats2half2_rn(o2, o3);
    uint2 u;
    u.x = *(uint32_t*)&a;
    u.y = *(uint32_t*)&bb;
    *(uint2*)&g_hf[(size_t)n * D_ + t * 4] = u;
}

// ============ warp-MMA fp16 GEMM: C[M,N] = A[M,K]*B[N,K]^T (fp32 accum) ============
// CTA 128x128, 8 warps of 64x32. K64 pairs over 6-stage (3 pair-slot) ring.
#define GSUB   (128 * 16)                 // fp16 elems per K16 sub-buffer
#define GCH    (2 * GSUB)                 // elems per K32 chunk (4096)
#define GMAT   (6 * GCH)                  // elems per matrix (6 stages)
#define GEMM_SMEM_BYTES (2 * GMAT * 2)    // 98304 B

__global__ __launch_bounds__(256) void gemm_f16(
    const __half* __restrict__ Af, const __half* __restrict__ Bf,
    float* __restrict__ C, int M, int N, int K)
{
    extern __shared__ __half smg[];
    __half* sA = smg;
    __half* sB = smg + GMAT;

    int tid = threadIdx.x;
    int warp = tid >> 5, lane = tid & 31;
    int m0 = blockIdx.y * 128, n0 = blockIdx.x * 128;
    int wm = (warp & 1) * 64, wn = (warp >> 1) * 32;

    int lrow = tid >> 1;
    int lch  = (tid & 1) * 8;
    uint32_t uA = smem_u32(sA), uB = smem_u32(sB);
    uint32_t dsto = (uint32_t)(lrow * 16 + lch) * 2;    // within a sub buffer

    const __half* gA = Af + (size_t)(m0 + lrow) * K + lch;
    const __half* gB = Bf + (size_t)(n0 + lrow) * K + lch;

    float d[4][4][4];
    #pragma unroll
    for (int mi = 0; mi < 4; mi++)
        #pragma unroll
        for (int ni = 0; ni < 4; ni++)
            #pragma unroll
            for (int r = 0; r < 4; r++) d[mi][ni][r] = 0.f;

    const int npair = K >> 6;           // K64 pairs (K=1024 -> 16)

    #define CHUNK_OFF(c) ((uint32_t)((((c) >> 1) % 3) * 2 + ((c) & 1)) * GCH)

    // prologue: pairs 0,1 (chunks 0..3), one commit per pair
    #pragma unroll
    for (int c = 0; c < 4; c++) {
        #pragma unroll
        for (int sub = 0; sub < 2; sub++) {
            uint32_t so = (CHUNK_OFF(c) + (uint32_t)(sub * GSUB)) * 2 + dsto;
            CP_ASYNC16(uA + so, gA + c * 32 + sub * 16);
            CP_ASYNC16(uB + so, gB + c * 32 + sub * 16);
        }
        if (c & 1) CP_COMMIT();
    }

    int ar = wm + (lane >> 2);
    int ac = (lane & 3) * 2;
    int br = wn + (lane >> 2);
    int bc = (lane & 3) * 2;

    for (int p = 0; p < npair; p++) {
        if (p == npair - 1) { CP_WAIT0(); } else { CP_WAIT1(); }
        __syncthreads();

        if (p + 2 < npair) {
            #pragma unroll
            for (int ch = 0; ch < 2; ch++) {
                int c = 2 * (p + 2) + ch;
                #pragma unroll
                for (int sub = 0; sub < 2; sub++) {
                    uint32_t so = (CHUNK_OFF(c) + (uint32_t)(sub * GSUB)) * 2 + dsto;
                    CP_ASYNC16(uA + so, gA + c * 32 + sub * 16);
                    CP_ASYNC16(uB + so, gB + c * 32 + sub * 16);
                }
            }
        }
        CP_COMMIT();

        #pragma unroll
        for (int ch = 0; ch < 2; ch++) {
            int c = 2 * p + ch;
            #pragma unroll
            for (int sub = 0; sub < 2; sub++) {
                const __half* pA = sA + CHUNK_OFF(c) + sub * GSUB;
                const __half* pB = sB + CHUNK_OFF(c) + sub * GSUB;

                uint32_t ah[4][4], bh[4][2];
                #pragma unroll
                for (int mi = 0; mi < 4; mi++) {
                    int r0 = (ar + mi * 16) * 16 + ac;
                    int r1 = r0 + 8 * 16;
                    ah[mi][0] = *(const uint32_t*)(pA + r0);
                    ah[mi][1] = *(const uint32_t*)(pA + r1);
                    ah[mi][2] = *(const uint32_t*)(pA + r0 + 8);
                    ah[mi][3] = *(const uint32_t*)(pA + r1 + 8);
                }
                #pragma unroll
                for (int ni = 0; ni < 4; ni++) {
                    int c0 = (br + ni * 8) * 16 + bc;
                    bh[ni][0] = *(const uint32_t*)(pB + c0);
                    bh[ni][1] = *(const uint32_t*)(pB + c0 + 8);
                }

                #pragma unroll
                for (int mi = 0; mi < 4; mi++)
                    #pragma unroll
                    for (int ni = 0; ni < 4; ni++)
                        MMAF16(d[mi][ni], ah[mi], bh[ni]);
            }
        }
    }

    #pragma unroll
    for (int mi = 0; mi < 4; mi++) {
        int r = m0 + wm + mi * 16 + (lane >> 2);
        #pragma unroll
        for (int ni = 0; ni < 4; ni++) {
            int c = n0 + wn + ni * 8 + (lane & 3) * 2;
            *(float2*)&C[(size_t)r * N + c] = make_float2(d[mi][ni][0], d[mi][ni][1]);
            *(float2*)&C[(size_t)(r + 8) * N + c] = make_float2(d[mi][ni][2], d[mi][ni][3]);
        }
    }
}

// ---------- fused QK-LN+RoPE (blocks [0,4096)) + V transpose ([4096,6144)) ----------
__global__ void qkrope_vt_kernel(const float* __restrict__ qw,
                                 const float* __restrict__ kw) {
    int bid = blockIdx.x;
    int t = threadIdx.x;

    if (bid >= 4096) {
        // ---- V transpose: g_qkv v-part -> [BH,DH,L] fp16 ----
        __shared__ float tile[64][33];
        int bid2 = bid - 4096;
        int bh = bid2 >> 6;                 // 0..31
        int b = bh >> 4, h = bh & 15;
        int l0 = (bid2 & 63) * 32;
        int tx = t & 31, ty = t >> 5;
        #pragma unroll
        for (int i = 0; i < 4; i++) {
            int l = l0 + ty + i * 8;
            const float* row = g_qkv + (size_t)(b * L_ + l) * D3 + 2 * D_ + h * DH;
            tile[tx][ty + i * 8]      = row[tx];
            tile[tx + 32][ty + i * 8] = row[tx + 32];
        }
        __syncthreads();
        #pragma unroll
        for (int i = 0; i < 8; i++) {
            int d = ty + i * 8;
            size_t o = (size_t)(bh * DH + d) * L_ + l0 + tx;
            g_vtf[o] = __float2half_rn(tile[d][tx]);
        }
        return;
    }

    // ---- QK-LN + RoPE ----
    int n = bid;
    int b = n >> 11;
    int l = n & 2047;
    const float* q = g_qkv + (size_t)n * D3;
    const float* k = q + D_;

    float4 qv = *(const float4*)&q[t * 4];
    float4 kv = *(const float4*)&k[t * 4];
    float qs  = qv.x + qv.y + qv.z + qv.w;
    float qs2 = qv.x*qv.x + qv.y*qv.y + qv.z*qv.z + qv.w*qv.w;
    float ks  = kv.x + kv.y + kv.z + kv.w;
    float ks2 = kv.x*kv.x + kv.y*kv.y + kv.z*kv.z + kv.w*kv.w;
    #pragma unroll
    for (int o = 16; o >= 1; o >>= 1) {
        qs  += __shfl_xor_sync(0xffffffffu, qs,  o);
        qs2 += __shfl_xor_sync(0xffffffffu, qs2, o);
        ks  += __shfl_xor_sync(0xffffffffu, ks,  o);
        ks2 += __shfl_xor_sync(0xffffffffu, ks2, o);
    }
    __shared__ float red[4][8];
    __shared__ float stat[4];
    int lane = t & 31, wp = t >> 5;
    if (lane == 0) { red[0][wp]=qs; red[1][wp]=qs2; red[2][wp]=ks; red[3][wp]=ks2; }
    __syncthreads();
    if (t == 0) {
        float a=0,c=0,e=0,f=0;
        #pragma unroll
        for (int i=0;i<8;i++){a+=red[0][i];c+=red[1][i];e+=red[2][i];f+=red[3][i];}
        float qmu=a*(1.f/D_), qvr=c*(1.f/D_)-qmu*qmu;
        float kmu=e*(1.f/D_), kvr=f*(1.f/D_)-kmu*kmu;
        stat[0]=qmu; stat[1]=rsqrtf(qvr+EPS);
        stat[2]=kmu; stat[3]=rsqrtf(kvr+EPS);
    }
    __syncthreads();
    float qmu=stat[0], qrs=stat[1], kmu=stat[2], krs=stat[3];
    float4 qwv = *(const float4*)&qw[t*4];
    float4 kwv = *(const float4*)&kw[t*4];
    float qnv[4], knv[4];
    qnv[0]=(qv.x-qmu)*qrs*qwv.x; qnv[1]=(qv.y-qmu)*qrs*qwv.y;
    qnv[2]=(qv.z-qmu)*qrs*qwv.z; qnv[3]=(qv.w-qmu)*qrs*qwv.w;
    knv[0]=(kv.x-kmu)*krs*kwv.x; knv[1]=(kv.y-kmu)*krs*kwv.y;
    knv[2]=(kv.z-kmu)*krs*kwv.z; knv[3]=(kv.w-kmu)*krs*kwv.w;

    // RoPE partner (d +/- 32) lives exactly 8 lanes away in the same warp
    float qp[4], kp[4];
    #pragma unroll
    for (int ii = 0; ii < 4; ii++) {
        qp[ii] = __shfl_xor_sync(0xffffffffu, qnv[ii], 8);
        kp[ii] = __shfl_xor_sync(0xffffffffu, knv[ii], 8);
    }
    bool hiHalf = (t & 8) != 0;     // j0 >= 32
    int d0 = t * 4;
    int hh = d0 >> 6;
    int j0 = d0 & 63;
    int f0 = d0 & 31;
    float qo[4], ko[4];
    #pragma unroll
    for (int ii = 0; ii < 4; ii++) {
        float c = g_cos[l * 32 + f0 + ii];
        float s = g_sin[l * 32 + f0 + ii];
        if (!hiHalf) {
            qo[ii] = qnv[ii] * c - qp[ii] * s;
            ko[ii] = knv[ii] * c - kp[ii] * s;
        } else {
            qo[ii] = qnv[ii] * c + qp[ii] * s;
            ko[ii] = knv[ii] * c + kp[ii] * s;
        }
        qo[ii] *= 0.125f;   // fold softmax scale into q
    }
    size_t oidx = (((size_t)(b * H_ + hh)) * L_ + l) * DH + j0;
    __half2 q01 = __floats2half2_rn(qo[0], qo[1]);
    __half2 q23 = __floats2half2_rn(qo[2], qo[3]);
    __half2 k01 = __floats2half2_rn(ko[0], ko[1]);
    __half2 k23 = __floats2half2_rn(ko[2], ko[3]);
    uint2 uq, uk;
    uq.x = *(uint32_t*)&q01; uq.y = *(uint32_t*)&q23;
    uk.x = *(uint32_t*)&k01; uk.y = *(uint32_t*)&k23;
    *(uint2*)&g_qf[oidx] = uq;
    *(uint2*)&g_kf[oidx] = uk;
}

// ---------------- flash attention on mma.sync (fp16 single-term) ----------------
// Q staging smem ALIASES KV buffer 1: Q is register-resident before the first
// prefetch into that region. Layout: [0,18432) = KV buf1 (K,V) / Q staging;
// [18432,36864) = KV buf0; [36864,+512) = seq-id slots.
#define KPAD 72
#define A4_TILE 9216
#define A4_BUF  18432
#define A4_SK   36864
#define ATT4_SMEM (A4_SK + 512)

__global__ __launch_bounds__(128) void attn_mma(const int* __restrict__ seq_id) {
    extern __shared__ char sm[];
    const uint32_t sbase = smem_u32(sm);
    int tid = threadIdx.x, lane = tid & 31, w = tid >> 5;
    int qt = blockIdx.x, h = blockIdx.y, b = blockIdx.z;
    int bh = b * H_ + h;
    int row0 = qt * 64;

    const __half* gQf = g_qf + ((size_t)bh * L_ + row0) * DH;
    const __half* gKf = g_kf + (size_t)bh * L_ * DH;
    const __half* gVf = g_vtf + (size_t)bh * DH * L_;

    // ---- valid k-tile range (contiguous because seq_id is sorted) ----
    int q_lo = seq_id[b * L_ + row0];
    int q_hi = seq_id[b * L_ + row0 + 63];
    unsigned vmask;
    {
        int klo = seq_id[b * L_ + lane * 64];
        int khi = seq_id[b * L_ + lane * 64 + 63];
        bool ok = (khi >= q_lo) && (klo <= q_hi);
        vmask = __ballot_sync(0xffffffffu, ok);
    }
    int tlo = __ffs(vmask) - 1;
    int thi = 31 - __clz(vmask);

    int lrow = tid >> 1;          // 0..63
    int cb0  = (tid & 1) * 4;     // chunk base (16B chunks)

    // ---- prologue: Q tile into buf1 region (offset 0) ----
    #pragma unroll
    for (int c = 0; c < 4; c++) {
        int ch = cb0 + c;
        uint32_t so = (uint32_t)(lrow * KPAD + ch * 8) * 2;
        CP_ASYNC16(sbase + so, gQf + lrow * DH + ch * 8);
    }
    CP_COMMIT();
    // ---- K/V tile tlo into buf0 region (offset A4_BUF) ----
    {
        int col0 = tlo * 64;
        uint32_t dst = sbase + A4_BUF;
        #pragma unroll
        for (int c = 0; c < 4; c++) {
            int ch = cb0 + c;
            uint32_t so = (uint32_t)(lrow * KPAD + ch * 8) * 2;
            CP_ASYNC16(dst + so,           gKf + (size_t)(col0 + lrow) * DH + ch * 8);
            CP_ASYNC16(dst + A4_TILE + so, gVf + (size_t)lrow * L_ + col0 + ch * 8);
        }
    }
    CP_COMMIT();
    if (tid < 64) ((int*)(sm + A4_SK))[tid] = seq_id[b * L_ + tlo * 64 + tid];
    int sq0 = seq_id[b * L_ + row0 + w * 16 + (lane >> 2)];
    int sq1 = seq_id[b * L_ + row0 + w * 16 + (lane >> 2) + 8];

    CP_WAIT1();                 // Q group complete (KV0 may be in flight)
    __syncthreads();

    // ---- extract Q fragments (held for whole kernel); frees buf1 region ----
    uint32_t qf[4][4];
    {
        const __half* sQ = (const __half*)sm;
        #pragma unroll
        for (int s = 0; s < 4; s++) {
            int base = (w * 16 + (lane >> 2)) * KPAD + s * 16 + (lane & 3) * 2;
            qf[s][0] = *(const uint32_t*)(sQ + base);
            qf[s][1] = *(const uint32_t*)(sQ + base + 8 * KPAD);
            qf[s][2] = *(const uint32_t*)(sQ + base + 8);
            qf[s][3] = *(const uint32_t*)(sQ + base + 8 * KPAD + 8);
        }
    }

    float m0 = -1e30f, m1 = -1e30f, l0 = 0.f, l1 = 0.f;
    float pv[8][4];
    #pragma unroll
    for (int j = 0; j < 8; j++)
        #pragma unroll
        for (int r = 0; r < 4; r++) pv[j][r] = 0.f;

    for (int it = tlo; it <= thi; it++) {
        int buf = (it - tlo) & 1;               // 0 -> region A4_BUF, 1 -> region 0
        uint32_t kvb  = sbase + (buf ? 0u : (uint32_t)A4_BUF);
        uint32_t kvbn = sbase + (buf ? (uint32_t)A4_BUF : 0u);
        CP_WAIT0();
        __syncthreads();                         // Q frags extracted by all warps

        // prefetch next tile into the other region (overwrites Q on first iter)
        if (it + 1 <= thi) {
            int col0n = (it + 1) * 64;
            #pragma unroll
            for (int c = 0; c < 4; c++) {
                int ch = cb0 + c;
                uint32_t so = (uint32_t)(lrow * KPAD + ch * 8) * 2;
                CP_ASYNC16(kvbn + so,           gKf + (size_t)(col0n + lrow) * DH + ch * 8);
                CP_ASYNC16(kvbn + A4_TILE + so, gVf + (size_t)lrow * L_ + col0n + ch * 8);
            }
            if (tid < 64)
                ((int*)(sm + A4_SK))[(buf ^ 1) * 64 + tid] =
                    seq_id[b * L_ + col0n + tid];
        }
        CP_COMMIT();

        const __half* sK = (const __half*)(sm + (kvb - sbase));
        const __half* sV = sK + A4_TILE / 2;
        const int* skp = (const int*)(sm + A4_SK) + buf * 64;

        // ---- S = Q K^T (fp16 single) ----
        float sf[8][4];
        #pragma unroll
        for (int j = 0; j < 8; j++)
            #pragma unroll
            for (int r = 0; r < 4; r++) sf[j][r] = 0.f;
        #pragma unroll
        for (int s = 0; s < 4; s++) {
            #pragma unroll
            for (int j = 0; j < 8; j++) {
                int off = (j * 8 + (lane >> 2)) * KPAD + s * 16 + (lane & 3) * 2;
                uint32_t bf[2] = {*(const uint32_t*)(sK + off),
                                  *(const uint32_t*)(sK + off + 8)};
                MMAF16(sf[j], qf[s], bf);
            }
        }

        // ---- mask + online softmax (c-frag layout) ----
        int colb = (lane & 3) * 2;
        float nm0 = m0, nm1 = m1;
        #pragma unroll
        for (int j = 0; j < 8; j++) {
            int k0 = skp[8 * j + colb], k1 = skp[8 * j + colb + 1];
            sf[j][0] = (k0 == sq0) ? sf[j][0] : -2e30f;
            sf[j][1] = (k1 == sq0) ? sf[j][1] : -2e30f;
            sf[j][2] = (k0 == sq1) ? sf[j][2] : -2e30f;
            sf[j][3] = (k1 == sq1) ? sf[j][3] : -2e30f;
            nm0 = fmaxf(nm0, fmaxf(sf[j][0], sf[j][1]));
            nm1 = fmaxf(nm1, fmaxf(sf[j][2], sf[j][3]));
        }
        nm0 = fmaxf(nm0, __shfl_xor_sync(0xffffffffu, nm0, 1));
        nm0 = fmaxf(nm0, __shfl_xor_sync(0xffffffffu, nm0, 2));
        nm1 = fmaxf(nm1, __shfl_xor_sync(0xffffffffu, nm1, 1));
        nm1 = fmaxf(nm1, __shfl_xor_sync(0xffffffffu, nm1, 2));
        float a0 = __expf(m0 - nm0), a1 = __expf(m1 - nm1);
        m0 = nm0; m1 = nm1;

        float s0 = 0.f, s1 = 0.f;
        uint32_t ph[4][4];
        #pragma unroll
        for (int j = 0; j < 8; j++) {
            float p0 = __expf(sf[j][0] - m0), p1 = __expf(sf[j][1] - m0);
            float p2 = __expf(sf[j][2] - m1), p3 = __expf(sf[j][3] - m1);
            s0 += p0 + p1; s1 += p2 + p3;
            __half2 h01 = __floats2half2_rn(p0, p1);
            __half2 h23 = __floats2half2_rn(p2, p3);
            int s_ = j >> 1;
            int o  = (j & 1) * 2;
            ph[s_][o]     = *(uint32_t*)&h01;
            ph[s_][o + 1] = *(uint32_t*)&h23;
        }
        s0 += __shfl_xor_sync(0xffffffffu, s0, 1);
        s0 += __shfl_xor_sync(0xffffffffu, s0, 2);
        s1 += __shfl_xor_sync(0xffffffffu, s1, 1);
        s1 += __shfl_xor_sync(0xffffffffu, s1, 2);
        l0 = l0 * a0 + s0;
        l1 = l1 * a1 + s1;
        #pragma unroll
        for (int j = 0; j < 8; j++) {
            pv[j][0] *= a0; pv[j][1] *= a0; pv[j][2] *= a1; pv[j][3] *= a1;
        }

        // ---- PV (fp16 single), B = Vt[dh][c] ----
        #pragma unroll
        for (int s = 0; s < 4; s++) {
            #pragma unroll
            for (int j = 0; j < 8; j++) {
                int off = (j * 8 + (lane >> 2)) * KPAD + s * 16 + (lane & 3) * 2;
                uint32_t bf[2] = {*(const uint32_t*)(sV + off),
                                  *(const uint32_t*)(sV + off + 8)};
                MMAF16(pv[j], ph[s], bf);
            }
        }
    }

    // ---- epilogue: ctx / l -> fp16 [B,L,H,DH] ----
    float inv0 = 1.0f / l0, inv1 = 1.0f / l1;
    int r0g = row0 + w * 16 + (lane >> 2);
    #pragma unroll
    for (int j = 0; j < 8; j++) {
        int c = 8 * j + (lane & 3) * 2;
        size_t o0 = (((size_t)b * L_ + r0g) * H_ + h) * DH + c;
        size_t o1 = (((size_t)b * L_ + r0g + 8) * H_ + h) * DH + c;
        __half2 hx = __floats2half2_rn(pv[j][0] * inv0, pv[j][1] * inv0);
        __half2 hy = __floats2half2_rn(pv[j][2] * inv1, pv[j][3] * inv1);
        *(uint32_t*)&g_cf[o0] = *(uint32_t*)&hx;
        *(uint32_t*)&g_cf[o1] = *(uint32_t*)&hy;
    }
}

// ---------------- launch ----------------
extern "C" void kernel_launch(void* const* d_in, const int* in_sizes, int n_in,
                              void* d_out, int out_size) {
    const float* x      = (const float*)d_in[0];
    const int*   seq_id = (const int*)  d_in[1];
    const float* ln1_w  = (const float*)d_in[2];
    const float* ln1_b  = (const float*)d_in[3];
    const float* w_qkv  = (const float*)d_in[4];
    const float* q_ln_w = (const float*)d_in[5];
    const float* k_ln_w = (const float*)d_in[6];
    const float* out_w  = (const float*)d_in[7];
    float* out = (float*)d_out;

    void *phf, *pwqf, *powf, *pcf, *pqkv;
    cudaGetSymbolAddress(&phf,  g_hf);
    cudaGetSymbolAddress(&pwqf, g_wqf);
    cudaGetSymbolAddress(&powf, g_owf);
    cudaGetSymbolAddress(&pcf,  g_cf);
    cudaGetSymbolAddress(&pqkv, g_qkv);

    cudaFuncSetAttribute(attn_mma, cudaFuncAttributeMaxDynamicSharedMemorySize,
                         ATT4_SMEM);
    cudaFuncSetAttribute(gemm_f16, cudaFuncAttributeMaxDynamicSharedMemorySize,
                         GEMM_SMEM_BYTES);

    prep_kernel<<<8448, 256>>>(x, ln1_w, ln1_b, w_qkv, out_w);
    gemm_f16<<<dim3(D3 / 128, NT / 128), 256, GEMM_SMEM_BYTES>>>(
        (const __half*)phf, (const __half*)pwqf, (float*)pqkv, NT, D3, D_);
    qkrope_vt_kernel<<<6144, 256>>>(q_ln_w, k_ln_w);
    attn_mma<<<dim3(L_ / 64, H_, B_), 128, ATT4_SMEM>>>(seq_id);
    gemm_f16<<<dim3(D_ / 128, NT / 128), 256, GEMM_SMEM_BYTES>>>(
        (const __half*)pcf, (const __half*)powf, out, NT, D_, D_);
}

// round 15
// speedup vs baseline: 1.0242x; 1.0079x over previous
#include <cuda_runtime.h>
#include <cuda_bf16.h>
#include <cuda_fp16.h>
#include <cstdint>
#include <math.h>

// Problem constants
#define B_  2
#define L_  2048
#define NT  4096            // B*L tokens
#define D_  1024
#define H_  16
#define DH  64
#define D3  3072
#define EPS 1e-5f

// ---------------- scratch (device globals; no allocation) ----------------
__device__ __half g_hf[NT * D_];          // LN1 out (fp16)
__device__ __half g_wqf[D3 * D_];         // w_qkv (fp16)
__device__ __half g_owf[D_ * D_];         // out_w (fp16)
__device__ __half g_cf[NT * D_];          // ctx (fp16) [B,L,H,DH] == [NT,D]
__device__ __half g_qf[NT * D_];          // q (scaled, fp16) [BH,L,DH]
__device__ __half g_kf[NT * D_];          // k (fp16) [BH,L,DH]
__device__ __half g_vtf[NT * D_];         // v^T (fp16) [BH,DH,L]
__device__ float g_qkv[NT * D3];          // QKV gemm output [NT, 3D]
__device__ float g_cos[L_ * 32];
__device__ float g_sin[L_ * 32];

// ---------------- helpers ----------------
__device__ __forceinline__ uint32_t smem_u32(const void* p) {
    uint32_t a;
    asm("{ .reg .u64 t; cvta.to.shared.u64 t, %1; cvt.u32.u64 %0, t; }"
        : "=r"(a) : "l"(p));
    return a;
}
#define CP_ASYNC16(dst, src) \
    asm volatile("cp.async.cg.shared.global [%0], [%1], 16;" :: "r"(dst), "l"(src))
#define CP_COMMIT() asm volatile("cp.async.commit_group;" ::: "memory")
#define CP_WAIT0()  asm volatile("cp.async.wait_group 0;" ::: "memory")
#define CP_WAIT1()  asm volatile("cp.async.wait_group 1;" ::: "memory")

// fp16 mma
#define MMAF16(d, a, b) \
    asm volatile( \
        "mma.sync.aligned.m16n8k16.row.col.f32.f16.f16.f32 " \
        "{%0,%1,%2,%3}, {%4,%5,%6,%7}, {%8,%9}, {%0,%1,%2,%3};" \
        : "+f"((d)[0]), "+f"((d)[1]), "+f"((d)[2]), "+f"((d)[3]) \
        : "r"((a)[0]), "r"((a)[1]), "r"((a)[2]), "r"((a)[3]), \
          "r"((b)[0]), "r"((b)[1]))

// ---------------- fused prep: rope table + weight conv + LN1 ----------------
// grid: [0,256) rope | [256,3328) conv w_qkv | [3328,4352) conv out_w |
//       [4352,8448) ln1
__global__ void prep_kernel(const float* __restrict__ x,
                            const float* __restrict__ ln1w,
                            const float* __restrict__ ln1b,
                            const float* __restrict__ wq,
                            const float* __restrict__ ow) {
    int bid = blockIdx.x;
    int t = threadIdx.x;
    if (bid < 256) {
        int idx = bid * 256 + t;
        int l = idx >> 5;
        int j = idx & 31;
        float inv = powf(10000.0f, -(float)j / 32.0f);
        float ang = (float)l * inv;
        float s, c;
        sincosf(ang, &s, &c);
        g_cos[idx] = c;
        g_sin[idx] = s;
        return;
    }
    if (bid < 4352) {
        const float* src;
        __half* dst;
        int i;
        if (bid < 3328) { src = wq; dst = g_wqf; i = ((bid - 256) * 256 + t) * 4; }
        else            { src = ow; dst = g_owf; i = ((bid - 3328) * 256 + t) * 4; }
        float4 v = *(const float4*)&src[i];
        __half2 a = __floats2half2_rn(v.x, v.y);
        __half2 b = __floats2half2_rn(v.z, v.w);
        uint2 u;
        u.x = *(uint32_t*)&a;
        u.y = *(uint32_t*)&b;
        *(uint2*)&dst[i] = u;
        return;
    }
    // ---- ln1 ----
    int n = bid - 4352;
    const float* xr = x + (size_t)n * D_;
    float4 v = *(const float4*)&xr[t * 4];
    float s  = v.x + v.y + v.z + v.w;
    float s2 = v.x*v.x + v.y*v.y + v.z*v.z + v.w*v.w;
    #pragma unroll
    for (int o = 16; o >= 1; o >>= 1) {
        s  += __shfl_xor_sync(0xffffffffu, s,  o);
        s2 += __shfl_xor_sync(0xffffffffu, s2, o);
    }
    __shared__ float red[2][8];
    int lane = t & 31, wp = t >> 5;
    if (lane == 0) { red[0][wp] = s; red[1][wp] = s2; }
    __syncthreads();
    __shared__ float stat[2];
    if (t == 0) {
        float a = 0.f, c = 0.f;
        #pragma unroll
        for (int i = 0; i < 8; i++) { a += red[0][i]; c += red[1][i]; }
        float mu  = a * (1.0f / D_);
        float var = c * (1.0f / D_) - mu * mu;
        stat[0] = mu;
        stat[1] = rsqrtf(var + EPS);
    }
    __syncthreads();
    float mu = stat[0], rs = stat[1];
    float4 wv = *(const float4*)&ln1w[t * 4];
    float4 bv = *(const float4*)&ln1b[t * 4];
    float o0 = (v.x - mu) * rs * wv.x + bv.x;
    float o1 = (v.y - mu) * rs * wv.y + bv.y;
    float o2 = (v.z - mu) * rs * wv.z + bv.z;
    float o3 = (v.w - mu) * rs * wv.w + bv.w;
    __half2 a = __floats2half2_rn(o0, o1);
    __half2 bb = __floats2half2_rn(o2, o3);
    uint2 u;
    u.x = *(uint32_t*)&a;
    u.y = *(uint32_t*)&bb;
    *(uint2*)&g_hf[(size_t)n * D_ + t * 4] = u;
}

// ============ warp-MMA fp16 GEMM: C[M,N] = A[M,K]*B[N,K]^T (fp32 accum) ============
// CTA 128x128, 8 warps of 64x32. K64 pairs over 6-stage (3 pair-slot) ring.
#define GSUB   (128 * 16)                 // fp16 elems per K16 sub-buffer
#define GCH    (2 * GSUB)                 // elems per K32 chunk (4096)
#define GMAT   (6 * GCH)                  // elems per matrix (6 stages)
#define GEMM_SMEM_BYTES (2 * GMAT * 2)    // 98304 B

__global__ __launch_bounds__(256) void gemm_f16(
    const __half* __restrict__ Af, const __half* __restrict__ Bf,
    float* __restrict__ C, int M, int N, int K)
{
    extern __shared__ __half smg[];
    __half* sA = smg;
    __half* sB = smg + GMAT;

    int tid = threadIdx.x;
    int warp = tid >> 5, lane = tid & 31;
    int m0 = blockIdx.y * 128, n0 = blockIdx.x * 128;
    int wm = (warp & 1) * 64, wn = (warp >> 1) * 32;

    int lrow = tid >> 1;
    int lch  = (tid & 1) * 8;
    uint32_t uA = smem_u32(sA), uB = smem_u32(sB);
    uint32_t dsto = (uint32_t)(lrow * 16 + lch) * 2;    // within a sub buffer

    const __half* gA = Af + (size_t)(m0 + lrow) * K + lch;
    const __half* gB = Bf + (size_t)(n0 + lrow) * K + lch;

    float d[4][4][4];
    #pragma unroll
    for (int mi = 0; mi < 4; mi++)
        #pragma unroll
        for (int ni = 0; ni < 4; ni++)
            #pragma unroll
            for (int r = 0; r < 4; r++) d[mi][ni][r] = 0.f;

    const int npair = K >> 6;           // K64 pairs (K=1024 -> 16)

    #define CHUNK_OFF(c) ((uint32_t)((((c) >> 1) % 3) * 2 + ((c) & 1)) * GCH)

    // prologue: pairs 0,1 (chunks 0..3), one commit per pair
    #pragma unroll
    for (int c = 0; c < 4; c++) {
        #pragma unroll
        for (int sub = 0; sub < 2; sub++) {
            uint32_t so = (CHUNK_OFF(c) + (uint32_t)(sub * GSUB)) * 2 + dsto;
            CP_ASYNC16(uA + so, gA + c * 32 + sub * 16);
            CP_ASYNC16(uB + so, gB + c * 32 + sub * 16);
        }
        if (c & 1) CP_COMMIT();
    }

    int ar = wm + (lane >> 2);
    int ac = (lane & 3) * 2;
    int br = wn + (lane >> 2);
    int bc = (lane & 3) * 2;

    for (int p = 0; p < npair; p++) {
        if (p == npair - 1) { CP_WAIT0(); } else { CP_WAIT1(); }
        __syncthreads();

        if (p + 2 < npair) {
            #pragma unroll
            for (int ch = 0; ch < 2; ch++) {
                int c = 2 * (p + 2) + ch;
                #pragma unroll
                for (int sub = 0; sub < 2; sub++) {
                    uint32_t so = (CHUNK_OFF(c) + (uint32_t)(sub * GSUB)) * 2 + dsto;
                    CP_ASYNC16(uA + so, gA + c * 32 + sub * 16);
                    CP_ASYNC16(uB + so, gB + c * 32 + sub * 16);
                }
            }
        }
        CP_COMMIT();

        #pragma unroll
        for (int ch = 0; ch < 2; ch++) {
            int c = 2 * p + ch;
            #pragma unroll
            for (int sub = 0; sub < 2; sub++) {
                const __half* pA = sA + CHUNK_OFF(c) + sub * GSUB;
                const __half* pB = sB + CHUNK_OFF(c) + sub * GSUB;

                uint32_t ah[4][4], bh[4][2];
                #pragma unroll
                for (int mi = 0; mi < 4; mi++) {
                    int r0 = (ar + mi * 16) * 16 + ac;
                    int r1 = r0 + 8 * 16;
                    ah[mi][0] = *(const uint32_t*)(pA + r0);
                    ah[mi][1] = *(const uint32_t*)(pA + r1);
                    ah[mi][2] = *(const uint32_t*)(pA + r0 + 8);
                    ah[mi][3] = *(const uint32_t*)(pA + r1 + 8);
                }
                #pragma unroll
                for (int ni = 0; ni < 4; ni++) {
                    int c0 = (br + ni * 8) * 16 + bc;
                    bh[ni][0] = *(const uint32_t*)(pB + c0);
                    bh[ni][1] = *(const uint32_t*)(pB + c0 + 8);
                }

                #pragma unroll
                for (int mi = 0; mi < 4; mi++)
                    #pragma unroll
                    for (int ni = 0; ni < 4; ni++)
                        MMAF16(d[mi][ni], ah[mi], bh[ni]);
            }
        }
    }

    #pragma unroll
    for (int mi = 0; mi < 4; mi++) {
        int r = m0 + wm + mi * 16 + (lane >> 2);
        #pragma unroll
        for (int ni = 0; ni < 4; ni++) {
            int c = n0 + wn + ni * 8 + (lane & 3) * 2;
            *(float2*)&C[(size_t)r * N + c] = make_float2(d[mi][ni][0], d[mi][ni][1]);
            *(float2*)&C[(size_t)(r + 8) * N + c] = make_float2(d[mi][ni][2], d[mi][ni][3]);
        }
    }
}

// ---------- fused QK-LN+RoPE (blocks [0,4096)) + V transpose ([4096,6144)) ----------
__global__ void qkrope_vt_kernel(const float* __restrict__ qw,
                                 const float* __restrict__ kw) {
    int bid = blockIdx.x;
    int t = threadIdx.x;

    if (bid >= 4096) {
        // ---- V transpose: g_qkv v-part -> [BH,DH,L] fp16 ----
        __shared__ float tile[64][33];
        int bid2 = bid - 4096;
        int bh = bid2 >> 6;                 // 0..31
        int b = bh >> 4, h = bh & 15;
        int l0 = (bid2 & 63) * 32;
        int tx = t & 31, ty = t >> 5;
        #pragma unroll
        for (int i = 0; i < 4; i++) {
            int l = l0 + ty + i * 8;
            const float* row = g_qkv + (size_t)(b * L_ + l) * D3 + 2 * D_ + h * DH;
            tile[tx][ty + i * 8]      = row[tx];
            tile[tx + 32][ty + i * 8] = row[tx + 32];
        }
        __syncthreads();
        #pragma unroll
        for (int i = 0; i < 8; i++) {
            int d = ty + i * 8;
            size_t o = (size_t)(bh * DH + d) * L_ + l0 + tx;
            g_vtf[o] = __float2half_rn(tile[d][tx]);
        }
        return;
    }

    // ---- QK-LN + RoPE ----
    int n = bid;
    int b = n >> 11;
    int l = n & 2047;
    const float* q = g_qkv + (size_t)n * D3;
    const float* k = q + D_;

    float4 qv = *(const float4*)&q[t * 4];
    float4 kv = *(const float4*)&k[t * 4];
    float qs  = qv.x + qv.y + qv.z + qv.w;
    float qs2 = qv.x*qv.x + qv.y*qv.y + qv.z*qv.z + qv.w*qv.w;
    float ks  = kv.x + kv.y + kv.z + kv.w;
    float ks2 = kv.x*kv.x + kv.y*kv.y + kv.z*kv.z + kv.w*kv.w;
    #pragma unroll
    for (int o = 16; o >= 1; o >>= 1) {
        qs  += __shfl_xor_sync(0xffffffffu, qs,  o);
        qs2 += __shfl_xor_sync(0xffffffffu, qs2, o);
        ks  += __shfl_xor_sync(0xffffffffu, ks,  o);
        ks2 += __shfl_xor_sync(0xffffffffu, ks2, o);
    }
    __shared__ float red[4][8];
    __shared__ float stat[4];
    int lane = t & 31, wp = t >> 5;
    if (lane == 0) { red[0][wp]=qs; red[1][wp]=qs2; red[2][wp]=ks; red[3][wp]=ks2; }
    __syncthreads();
    if (t == 0) {
        float a=0,c=0,e=0,f=0;
        #pragma unroll
        for (int i=0;i<8;i++){a+=red[0][i];c+=red[1][i];e+=red[2][i];f+=red[3][i];}
        float qmu=a*(1.f/D_), qvr=c*(1.f/D_)-qmu*qmu;
        float kmu=e*(1.f/D_), kvr=f*(1.f/D_)-kmu*kmu;
        stat[0]=qmu; stat[1]=rsqrtf(qvr+EPS);
        stat[2]=kmu; stat[3]=rsqrtf(kvr+EPS);
    }
    __syncthreads();
    float qmu=stat[0], qrs=stat[1], kmu=stat[2], krs=stat[3];
    float4 qwv = *(const float4*)&qw[t*4];
    float4 kwv = *(const float4*)&kw[t*4];
    float qnv[4], knv[4];
    qnv[0]=(qv.x-qmu)*qrs*qwv.x; qnv[1]=(qv.y-qmu)*qrs*qwv.y;
    qnv[2]=(qv.z-qmu)*qrs*qwv.z; qnv[3]=(qv.w-qmu)*qrs*qwv.w;
    knv[0]=(kv.x-kmu)*krs*kwv.x; knv[1]=(kv.y-kmu)*krs*kwv.y;
    knv[2]=(kv.z-kmu)*krs*kwv.z; knv[3]=(kv.w-kmu)*krs*kwv.w;

    // RoPE partner (d +/- 32) lives exactly 8 lanes away in the same warp
    float qp[4], kp[4];
    #pragma unroll
    for (int ii = 0; ii < 4; ii++) {
        qp[ii] = __shfl_xor_sync(0xffffffffu, qnv[ii], 8);
        kp[ii] = __shfl_xor_sync(0xffffffffu, knv[ii], 8);
    }
    bool hiHalf = (t & 8) != 0;     // j0 >= 32
    int d0 = t * 4;
    int hh = d0 >> 6;
    int j0 = d0 & 63;
    int f0 = d0 & 31;
    float qo[4], ko[4];
    #pragma unroll
    for (int ii = 0; ii < 4; ii++) {
        float c = g_cos[l * 32 + f0 + ii];
        float s = g_sin[l * 32 + f0 + ii];
        if (!hiHalf) {
            qo[ii] = qnv[ii] * c - qp[ii] * s;
            ko[ii] = knv[ii] * c - kp[ii] * s;
        } else {
            qo[ii] = qnv[ii] * c + qp[ii] * s;
            ko[ii] = knv[ii] * c + kp[ii] * s;
        }
        qo[ii] *= 0.125f;   // fold softmax scale into q
    }
    size_t oidx = (((size_t)(b * H_ + hh)) * L_ + l) * DH + j0;
    __half2 q01 = __floats2half2_rn(qo[0], qo[1]);
    __half2 q23 = __floats2half2_rn(qo[2], qo[3]);
    __half2 k01 = __floats2half2_rn(ko[0], ko[1]);
    __half2 k23 = __floats2half2_rn(ko[2], ko[3]);
    uint2 uq, uk;
    uq.x = *(uint32_t*)&q01; uq.y = *(uint32_t*)&q23;
    uk.x = *(uint32_t*)&k01; uk.y = *(uint32_t*)&k23;
    *(uint2*)&g_qf[oidx] = uq;
    *(uint2*)&g_kf[oidx] = uk;
}

// ---------------- flash attention on mma.sync (fp16 single-term) ----------------
// Q-tile 128 rows, 8 warps (warp w -> rows w*16..w*16+15). One 64-col K/V tile
// feeds all 128 q-rows -> half the cp.async/L2 traffic per MMA vs 64-row tiles.
// Q staging smem ALIASES KV buffer 1 (Q is register-resident before the first
// prefetch into that region). Layout: [0,18432) buf1/Q; [18432,36864) buf0;
// [36864,+512) seq-id slots.
#define KPAD 72
#define A5_TILE 9216
#define A5_BUF  18432
#define A5_SK   36864
#define ATT5_SMEM (A5_SK + 512)

__global__ __launch_bounds__(256) void attn_mma(const int* __restrict__ seq_id) {
    extern __shared__ char sm[];
    const uint32_t sbase = smem_u32(sm);
    int tid = threadIdx.x, lane = tid & 31, w = tid >> 5;
    int qt = blockIdx.x, h = blockIdx.y, b = blockIdx.z;
    int bh = b * H_ + h;
    int row0 = qt * 128;

    const __half* gQf = g_qf + ((size_t)bh * L_ + row0) * DH;
    const __half* gKf = g_kf + (size_t)bh * L_ * DH;
    const __half* gVf = g_vtf + (size_t)bh * DH * L_;

    // ---- valid k-tile range (contiguous because seq_id is sorted) ----
    int q_lo = seq_id[b * L_ + row0];
    int q_hi = seq_id[b * L_ + row0 + 127];
    unsigned vmask;
    {
        int klo = seq_id[b * L_ + lane * 64];
        int khi = seq_id[b * L_ + lane * 64 + 63];
        bool ok = (khi >= q_lo) && (klo <= q_hi);
        vmask = __ballot_sync(0xffffffffu, ok);
    }
    int tlo = __ffs(vmask) - 1;
    int thi = 31 - __clz(vmask);

    // ---- prologue: Q tile (128 rows x 8 chunks = 1024 chunks / 256 thr) ----
    {
        int lrow = tid >> 1;           // 0..127
        int cb0  = (tid & 1) * 4;
        #pragma unroll
        for (int c = 0; c < 4; c++) {
            int ch = cb0 + c;
            uint32_t so = (uint32_t)(lrow * KPAD + ch * 8) * 2;
            CP_ASYNC16(sbase + so, gQf + lrow * DH + ch * 8);
        }
    }
    CP_COMMIT();
    // ---- K/V tile tlo into buf0: threads [0,128) load K, [128,256) load V ----
    int kvrow = (tid & 127) >> 1;      // 0..63
    int kvcb  = (tid & 1) * 4;
    bool isV  = tid >= 128;
    {
        int col0 = tlo * 64;
        uint32_t dst = sbase + A5_BUF + (isV ? (uint32_t)A5_TILE : 0u);
        #pragma unroll
        for (int c = 0; c < 4; c++) {
            int ch = kvcb + c;
            uint32_t so = (uint32_t)(kvrow * KPAD + ch * 8) * 2;
            const __half* src = isV ? gVf + (size_t)kvrow * L_ + col0 + ch * 8
                                    : gKf + (size_t)(col0 + kvrow) * DH + ch * 8;
            CP_ASYNC16(dst + so, src);
        }
    }
    CP_COMMIT();
    if (tid < 64) ((int*)(sm + A5_SK))[tid] = seq_id[b * L_ + tlo * 64 + tid];
    int sq0 = seq_id[b * L_ + row0 + w * 16 + (lane >> 2)];
    int sq1 = seq_id[b * L_ + row0 + w * 16 + (lane >> 2) + 8];

    CP_WAIT1();                 // Q group complete (KV0 may be in flight)
    __syncthreads();

    // ---- extract Q fragments (held for whole kernel); frees buf1 region ----
    uint32_t qf[4][4];
    {
        const __half* sQ = (const __half*)sm;
        #pragma unroll
        for (int s = 0; s < 4; s++) {
            int base = (w * 16 + (lane >> 2)) * KPAD + s * 16 + (lane & 3) * 2;
            qf[s][0] = *(const uint32_t*)(sQ + base);
            qf[s][1] = *(const uint32_t*)(sQ + base + 8 * KPAD);
            qf[s][2] = *(const uint32_t*)(sQ + base + 8);
            qf[s][3] = *(const uint32_t*)(sQ + base + 8 * KPAD + 8);
        }
    }

    float m0 = -1e30f, m1 = -1e30f, l0 = 0.f, l1 = 0.f;
    float pv[8][4];
    #pragma unroll
    for (int j = 0; j < 8; j++)
        #pragma unroll
        for (int r = 0; r < 4; r++) pv[j][r] = 0.f;

    for (int it = tlo; it <= thi; it++) {
        int buf = (it - tlo) & 1;               // 0 -> region A5_BUF, 1 -> region 0
        uint32_t kvb  = sbase + (buf ? 0u : (uint32_t)A5_BUF);
        uint32_t kvbn = sbase + (buf ? (uint32_t)A5_BUF : 0u);
        CP_WAIT0();
        __syncthreads();                         // Q frags extracted by all warps

        // prefetch next tile into the other region (overwrites Q on first iter)
        if (it + 1 <= thi) {
            int col0n = (it + 1) * 64;
            uint32_t dst = kvbn + (isV ? (uint32_t)A5_TILE : 0u);
            #pragma unroll
            for (int c = 0; c < 4; c++) {
                int ch = kvcb + c;
                uint32_t so = (uint32_t)(kvrow * KPAD + ch * 8) * 2;
                const __half* src = isV ? gVf + (size_t)kvrow * L_ + col0n + ch * 8
                                        : gKf + (size_t)(col0n + kvrow) * DH + ch * 8;
                CP_ASYNC16(dst + so, src);
            }
            if (tid < 64)
                ((int*)(sm + A5_SK))[(buf ^ 1) * 64 + tid] =
                    seq_id[b * L_ + col0n + tid];
        }
        CP_COMMIT();

        const __half* sK = (const __half*)(sm + (kvb - sbase));
        const __half* sV = sK + A5_TILE / 2;
        const int* skp = (const int*)(sm + A5_SK) + buf * 64;

        // ---- S = Q K^T (fp16 single) ----
        float sf[8][4];
        #pragma unroll
        for (int j = 0; j < 8; j++)
            #pragma unroll
            for (int r = 0; r < 4; r++) sf[j][r] = 0.f;
        #pragma unroll
        for (int s = 0; s < 4; s++) {
            #pragma unroll
            for (int j = 0; j < 8; j++) {
                int off = (j * 8 + (lane >> 2)) * KPAD + s * 16 + (lane & 3) * 2;
                uint32_t bf[2] = {*(const uint32_t*)(sK + off),
                                  *(const uint32_t*)(sK + off + 8)};
                MMAF16(sf[j], qf[s], bf);
            }
        }

        // ---- mask + online softmax (c-frag layout) ----
        int colb = (lane & 3) * 2;
        float nm0 = m0, nm1 = m1;
        #pragma unroll
        for (int j = 0; j < 8; j++) {
            int k0 = skp[8 * j + colb], k1 = skp[8 * j + colb + 1];
            sf[j][0] = (k0 == sq0) ? sf[j][0] : -2e30f;
            sf[j][1] = (k1 == sq0) ? sf[j][1] : -2e30f;
            sf[j][2] = (k0 == sq1) ? sf[j][2] : -2e30f;
            sf[j][3] = (k1 == sq1) ? sf[j][3] : -2e30f;
            nm0 = fmaxf(nm0, fmaxf(sf[j][0], sf[j][1]));
            nm1 = fmaxf(nm1, fmaxf(sf[j][2], sf[j][3]));
        }
        nm0 = fmaxf(nm0, __shfl_xor_sync(0xffffffffu, nm0, 1));
        nm0 = fmaxf(nm0, __shfl_xor_sync(0xffffffffu, nm0, 2));
        nm1 = fmaxf(nm1, __shfl_xor_sync(0xffffffffu, nm1, 1));
        nm1 = fmaxf(nm1, __shfl_xor_sync(0xffffffffu, nm1, 2));
        float a0 = __expf(m0 - nm0), a1 = __expf(m1 - nm1);
        m0 = nm0; m1 = nm1;

        float s0 = 0.f, s1 = 0.f;
        uint32_t ph[4][4];
        #pragma unroll
        for (int j = 0; j < 8; j++) {
            float p0 = __expf(sf[j][0] - m0), p1 = __expf(sf[j][1] - m0);
            float p2 = __expf(sf[j][2] - m1), p3 = __expf(sf[j][3] - m1);
            s0 += p0 + p1; s1 += p2 + p3;
            __half2 h01 = __floats2half2_rn(p0, p1);
            __half2 h23 = __floats2half2_rn(p2, p3);
            int s_ = j >> 1;
            int o  = (j & 1) * 2;
            ph[s_][o]     = *(uint32_t*)&h01;
            ph[s_][o + 1] = *(uint32_t*)&h23;
        }
        s0 += __shfl_xor_sync(0xffffffffu, s0, 1);
        s0 += __shfl_xor_sync(0xffffffffu, s0, 2);
        s1 += __shfl_xor_sync(0xffffffffu, s1, 1);
        s1 += __shfl_xor_sync(0xffffffffu, s1, 2);
        l0 = l0 * a0 + s0;
        l1 = l1 * a1 + s1;
        #pragma unroll
        for (int j = 0; j < 8; j++) {
            pv[j][0] *= a0; pv[j][1] *= a0; pv[j][2] *= a1; pv[j][3] *= a1;
        }

        // ---- PV (fp16 single), B = Vt[dh][c] ----
        #pragma unroll
        for (int s = 0; s < 4; s++) {
            #pragma unroll
            for (int j = 0; j < 8; j++) {
                int off = (j * 8 + (lane >> 2)) * KPAD + s * 16 + (lane & 3) * 2;
                uint32_t bf[2] = {*(const uint32_t*)(sV + off),
                                  *(const uint32_t*)(sV + off + 8)};
                MMAF16(pv[j], ph[s], bf);
            }
        }
    }

    // ---- epilogue: ctx / l -> fp16 [B,L,H,DH] ----
    float inv0 = 1.0f / l0, inv1 = 1.0f / l1;
    int r0g = row0 + w * 16 + (lane >> 2);
    #pragma unroll
    for (int j = 0; j < 8; j++) {
        int c = 8 * j + (lane & 3) * 2;
        size_t o0 = (((size_t)b * L_ + r0g) * H_ + h) * DH + c;
        size_t o1 = (((size_t)b * L_ + r0g + 8) * H_ + h) * DH + c;
        __half2 hx = __floats2half2_rn(pv[j][0] * inv0, pv[j][1] * inv0);
        __half2 hy = __floats2half2_rn(pv[j][2] * inv1, pv[j][3] * inv1);
        *(uint32_t*)&g_cf[o0] = *(uint32_t*)&hx;
        *(uint32_t*)&g_cf[o1] = *(uint32_t*)&hy;
    }
}

// ---------------- launch ----------------
extern "C" void kernel_launch(void* const* d_in, const int* in_sizes, int n_in,
                              void* d_out, int out_size) {
    const float* x      = (const float*)d_in[0];
    const int*   seq_id = (const int*)  d_in[1];
    const float* ln1_w  = (const float*)d_in[2];
    const float* ln1_b  = (const float*)d_in[3];
    const float* w_qkv  = (const float*)d_in[4];
    const float* q_ln_w = (const float*)d_in[5];
    const float* k_ln_w = (const float*)d_in[6];
    const float* out_w  = (const float*)d_in[7];
    float* out = (float*)d_out;

    void *phf, *pwqf, *powf, *pcf, *pqkv;
    cudaGetSymbolAddress(&phf,  g_hf);
    cudaGetSymbolAddress(&pwqf, g_wqf);
    cudaGetSymbolAddress(&powf, g_owf);
    cudaGetSymbolAddress(&pcf,  g_cf);
    cudaGetSymbolAddress(&pqkv, g_qkv);

    cudaFuncSetAttribute(attn_mma, cudaFuncAttributeMaxDynamicSharedMemorySize,
                         ATT5_SMEM);
    cudaFuncSetAttribute(gemm_f16, cudaFuncAttributeMaxDynamicSharedMemorySize,
                         GEMM_SMEM_BYTES);

    prep_kernel<<<8448, 256>>>(x, ln1_w, ln1_b, w_qkv, out_w);
    gemm_f16<<<dim3(D3 / 128, NT / 128), 256, GEMM_SMEM_BYTES>>>(
        (const __half*)phf, (const __half*)pwqf, (float*)pqkv, NT, D3, D_);
    qkrope_vt_kernel<<<6144, 256>>>(q_ln_w, k_ln_w);
    attn_mma<<<dim3(L_ / 128, H_, B_), 256, ATT5_SMEM>>>(seq_id);
    gemm_f16<<<dim3(D_ / 128, NT / 128), 256, GEMM_SMEM_BYTES>>>(
        (const __half*)pcf, (const __half*)powf, out, NT, D_, D_);
}

// round 16
// speedup vs baseline: 1.0327x; 1.0083x over previous
#include <cuda_runtime.h>
#include <cuda_bf16.h>
#include <cuda_fp16.h>
#include <cstdint>
#include <math.h>

// Problem constants
#define B_  2
#define L_  2048
#define NT  4096            // B*L tokens
#define D_  1024
#define H_  16
#define DH  64
#define D3  3072
#define EPS 1e-5f

// ---------------- scratch (device globals; no allocation) ----------------
__device__ __half g_hf[NT * D_];          // LN1 out (fp16)
__device__ __half g_wqf[D3 * D_];         // w_qkv (fp16)
__device__ __half g_owf[D_ * D_];         // out_w (fp16)
__device__ __half g_cf[NT * D_];          // ctx (fp16) [B,L,H,DH] == [NT,D]
__device__ __half g_qf[NT * D_];          // q (scaled, fp16) [BH,L,DH]
__device__ __half g_kf[NT * D_];          // k (fp16) [BH,L,DH]
__device__ __half g_vtf[NT * D_];         // v^T (fp16) [BH,DH,L]
__device__ __half g_qkvh[NT * D3];        // QKV gemm output (fp16) [NT, 3D]
__device__ float g_cos[L_ * 32];
__device__ float g_sin[L_ * 32];

// ---------------- helpers ----------------
__device__ __forceinline__ uint32_t smem_u32(const void* p) {
    uint32_t a;
    asm("{ .reg .u64 t; cvta.to.shared.u64 t, %1; cvt.u32.u64 %0, t; }"
        : "=r"(a) : "l"(p));
    return a;
}
#define CP_ASYNC16(dst, src) \
    asm volatile("cp.async.cg.shared.global [%0], [%1], 16;" :: "r"(dst), "l"(src))
#define CP_COMMIT() asm volatile("cp.async.commit_group;" ::: "memory")
#define CP_WAIT0()  asm volatile("cp.async.wait_group 0;" ::: "memory")
#define CP_WAIT1()  asm volatile("cp.async.wait_group 1;" ::: "memory")

// fp16 mma
#define MMAF16(d, a, b) \
    asm volatile( \
        "mma.sync.aligned.m16n8k16.row.col.f32.f16.f16.f32 " \
        "{%0,%1,%2,%3}, {%4,%5,%6,%7}, {%8,%9}, {%0,%1,%2,%3};" \
        : "+f"((d)[0]), "+f"((d)[1]), "+f"((d)[2]), "+f"((d)[3]) \
        : "r"((a)[0]), "r"((a)[1]), "r"((a)[2]), "r"((a)[3]), \
          "r"((b)[0]), "r"((b)[1]))

// ---------------- fused prep: rope table + weight conv + LN1 ----------------
// grid: [0,256) rope | [256,3328) conv w_qkv | [3328,4352) conv out_w |
//       [4352,8448) ln1
__global__ void prep_kernel(const float* __restrict__ x,
                            const float* __restrict__ ln1w,
                            const float* __restrict__ ln1b,
                            const float* __restrict__ wq,
                            const float* __restrict__ ow) {
    int bid = blockIdx.x;
    int t = threadIdx.x;
    if (bid < 256) {
        int idx = bid * 256 + t;
        int l = idx >> 5;
        int j = idx & 31;
        float inv = powf(10000.0f, -(float)j / 32.0f);
        float ang = (float)l * inv;
        float s, c;
        sincosf(ang, &s, &c);
        g_cos[idx] = c;
        g_sin[idx] = s;
        return;
    }
    if (bid < 4352) {
        const float* src;
        __half* dst;
        int i;
        if (bid < 3328) { src = wq; dst = g_wqf; i = ((bid - 256) * 256 + t) * 4; }
        else            { src = ow; dst = g_owf; i = ((bid - 3328) * 256 + t) * 4; }
        float4 v = *(const float4*)&src[i];
        __half2 a = __floats2half2_rn(v.x, v.y);
        __half2 b = __floats2half2_rn(v.z, v.w);
        uint2 u;
        u.x = *(uint32_t*)&a;
        u.y = *(uint32_t*)&b;
        *(uint2*)&dst[i] = u;
        return;
    }
    // ---- ln1 ----
    int n = bid - 4352;
    const float* xr = x + (size_t)n * D_;
    float4 v = *(const float4*)&xr[t * 4];
    float s  = v.x + v.y + v.z + v.w;
    float s2 = v.x*v.x + v.y*v.y + v.z*v.z + v.w*v.w;
    #pragma unroll
    for (int o = 16; o >= 1; o >>= 1) {
        s  += __shfl_xor_sync(0xffffffffu, s,  o);
        s2 += __shfl_xor_sync(0xffffffffu, s2, o);
    }
    __shared__ float red[2][8];
    int lane = t & 31, wp = t >> 5;
    if (lane == 0) { red[0][wp] = s; red[1][wp] = s2; }
    __syncthreads();
    __shared__ float stat[2];
    if (t == 0) {
        float a = 0.f, c = 0.f;
        #pragma unroll
        for (int i = 0; i < 8; i++) { a += red[0][i]; c += red[1][i]; }
        float mu  = a * (1.0f / D_);
        float var = c * (1.0f / D_) - mu * mu;
        stat[0] = mu;
        stat[1] = rsqrtf(var + EPS);
    }
    __syncthreads();
    float mu = stat[0], rs = stat[1];
    float4 wv = *(const float4*)&ln1w[t * 4];
    float4 bv = *(const float4*)&ln1b[t * 4];
    float o0 = (v.x - mu) * rs * wv.x + bv.x;
    float o1 = (v.y - mu) * rs * wv.y + bv.y;
    float o2 = (v.z - mu) * rs * wv.z + bv.z;
    float o3 = (v.w - mu) * rs * wv.w + bv.w;
    __half2 a = __floats2half2_rn(o0, o1);
    __half2 bb = __floats2half2_rn(o2, o3);
    uint2 u;
    u.x = *(uint32_t*)&a;
    u.y = *(uint32_t*)&bb;
    *(uint2*)&g_hf[(size_t)n * D_ + t * 4] = u;
}

// ============ warp-MMA fp16 GEMM: C[M,N] = A[M,K]*B[N,K]^T (fp32 accum) ============
// CTA 128x128, 8 warps of 64x32. K64 pairs over 6-stage (3 pair-slot) ring.
// outHalf=1: store __half2 pairs; outHalf=0: store fp32 float2 pairs.
#define GSUB   (128 * 16)                 // fp16 elems per K16 sub-buffer
#define GCH    (2 * GSUB)                 // elems per K32 chunk (4096)
#define GMAT   (6 * GCH)                  // elems per matrix (6 stages)
#define GEMM_SMEM_BYTES (2 * GMAT * 2)    // 98304 B

__global__ __launch_bounds__(256) void gemm_f16(
    const __half* __restrict__ Af, const __half* __restrict__ Bf,
    void* __restrict__ Cv, int M, int N, int K, int outHalf)
{
    extern __shared__ __half smg[];
    __half* sA = smg;
    __half* sB = smg + GMAT;

    int tid = threadIdx.x;
    int warp = tid >> 5, lane = tid & 31;
    int m0 = blockIdx.y * 128, n0 = blockIdx.x * 128;
    int wm = (warp & 1) * 64, wn = (warp >> 1) * 32;

    int lrow = tid >> 1;
    int lch  = (tid & 1) * 8;
    uint32_t uA = smem_u32(sA), uB = smem_u32(sB);
    uint32_t dsto = (uint32_t)(lrow * 16 + lch) * 2;    // within a sub buffer

    const __half* gA = Af + (size_t)(m0 + lrow) * K + lch;
    const __half* gB = Bf + (size_t)(n0 + lrow) * K + lch;

    float d[4][4][4];
    #pragma unroll
    for (int mi = 0; mi < 4; mi++)
        #pragma unroll
        for (int ni = 0; ni < 4; ni++)
            #pragma unroll
            for (int r = 0; r < 4; r++) d[mi][ni][r] = 0.f;

    const int npair = K >> 6;           // K64 pairs (K=1024 -> 16)

    #define CHUNK_OFF(c) ((uint32_t)((((c) >> 1) % 3) * 2 + ((c) & 1)) * GCH)

    // prologue: pairs 0,1 (chunks 0..3), one commit per pair
    #pragma unroll
    for (int c = 0; c < 4; c++) {
        #pragma unroll
        for (int sub = 0; sub < 2; sub++) {
            uint32_t so = (CHUNK_OFF(c) + (uint32_t)(sub * GSUB)) * 2 + dsto;
            CP_ASYNC16(uA + so, gA + c * 32 + sub * 16);
            CP_ASYNC16(uB + so, gB + c * 32 + sub * 16);
        }
        if (c & 1) CP_COMMIT();
    }

    int ar = wm + (lane >> 2);
    int ac = (lane & 3) * 2;
    int br = wn + (lane >> 2);
    int bc = (lane & 3) * 2;

    for (int p = 0; p < npair; p++) {
        if (p == npair - 1) { CP_WAIT0(); } else { CP_WAIT1(); }
        __syncthreads();

        if (p + 2 < npair) {
            #pragma unroll
            for (int ch = 0; ch < 2; ch++) {
                int c = 2 * (p + 2) + ch;
                #pragma unroll
                for (int sub = 0; sub < 2; sub++) {
                    uint32_t so = (CHUNK_OFF(c) + (uint32_t)(sub * GSUB)) * 2 + dsto;
                    CP_ASYNC16(uA + so, gA + c * 32 + sub * 16);
                    CP_ASYNC16(uB + so, gB + c * 32 + sub * 16);
                }
            }
        }
        CP_COMMIT();

        #pragma unroll
        for (int ch = 0; ch < 2; ch++) {
            int c = 2 * p + ch;
            #pragma unroll
            for (int sub = 0; sub < 2; sub++) {
                const __half* pA = sA + CHUNK_OFF(c) + sub * GSUB;
                const __half* pB = sB + CHUNK_OFF(c) + sub * GSUB;

                uint32_t ah[4][4], bh[4][2];
                #pragma unroll
                for (int mi = 0; mi < 4; mi++) {
                    int r0 = (ar + mi * 16) * 16 + ac;
                    int r1 = r0 + 8 * 16;
                    ah[mi][0] = *(const uint32_t*)(pA + r0);
                    ah[mi][1] = *(const uint32_t*)(pA + r1);
                    ah[mi][2] = *(const uint32_t*)(pA + r0 + 8);
                    ah[mi][3] = *(const uint32_t*)(pA + r1 + 8);
                }
                #pragma unroll
                for (int ni = 0; ni < 4; ni++) {
                    int c0 = (br + ni * 8) * 16 + bc;
                    bh[ni][0] = *(const uint32_t*)(pB + c0);
                    bh[ni][1] = *(const uint32_t*)(pB + c0 + 8);
                }

                #pragma unroll
                for (int mi = 0; mi < 4; mi++)
                    #pragma unroll
                    for (int ni = 0; ni < 4; ni++)
                        MMAF16(d[mi][ni], ah[mi], bh[ni]);
            }
        }
    }

    if (outHalf) {
        __half* Ch = (__half*)Cv;
        #pragma unroll
        for (int mi = 0; mi < 4; mi++) {
            int r = m0 + wm + mi * 16 + (lane >> 2);
            #pragma unroll
            for (int ni = 0; ni < 4; ni++) {
                int c = n0 + wn + ni * 8 + (lane & 3) * 2;
                __half2 ha = __floats2half2_rn(d[mi][ni][0], d[mi][ni][1]);
                __half2 hb = __floats2half2_rn(d[mi][ni][2], d[mi][ni][3]);
                *(uint32_t*)&Ch[(size_t)r * N + c]       = *(uint32_t*)&ha;
                *(uint32_t*)&Ch[(size_t)(r + 8) * N + c] = *(uint32_t*)&hb;
            }
        }
    } else {
        float* C = (float*)Cv;
        #pragma unroll
        for (int mi = 0; mi < 4; mi++) {
            int r = m0 + wm + mi * 16 + (lane >> 2);
            #pragma unroll
            for (int ni = 0; ni < 4; ni++) {
                int c = n0 + wn + ni * 8 + (lane & 3) * 2;
                *(float2*)&C[(size_t)r * N + c] = make_float2(d[mi][ni][0], d[mi][ni][1]);
                *(float2*)&C[(size_t)(r + 8) * N + c] = make_float2(d[mi][ni][2], d[mi][ni][3]);
            }
        }
    }
}

// ---------- fused QK-LN+RoPE (blocks [0,4096)) + V transpose ([4096,6144)) ----------
__global__ void qkrope_vt_kernel(const float* __restrict__ qw,
                                 const float* __restrict__ kw) {
    int bid = blockIdx.x;
    int t = threadIdx.x;

    if (bid >= 4096) {
        // ---- V transpose: g_qkvh v-part (fp16) -> [BH,DH,L] fp16 ----
        __shared__ __half tileh[64][34];
        int bid2 = bid - 4096;
        int bh = bid2 >> 6;                 // 0..31
        int b = bh >> 4, h = bh & 15;
        int l0 = (bid2 & 63) * 32;
        int tx = t & 31, ty = t >> 5;
        #pragma unroll
        for (int i = 0; i < 4; i++) {
            int l = l0 + ty + i * 8;
            const __half* row = g_qkvh + (size_t)(b * L_ + l) * D3 + 2 * D_ + h * DH;
            tileh[tx][ty + i * 8]      = row[tx];
            tileh[tx + 32][ty + i * 8] = row[tx + 32];
        }
        __syncthreads();
        #pragma unroll
        for (int i = 0; i < 8; i++) {
            int d = ty + i * 8;
            size_t o = (size_t)(bh * DH + d) * L_ + l0 + tx;
            g_vtf[o] = tileh[d][tx];
        }
        return;
    }

    // ---- QK-LN + RoPE (reads fp16 qkv) ----
    int n = bid;
    int b = n >> 11;
    int l = n & 2047;
    const __half* q = g_qkvh + (size_t)n * D3;
    const __half* k = q + D_;

    uint2 uqr = *(const uint2*)&q[t * 4];
    uint2 ukr = *(const uint2*)&k[t * 4];
    float2 qf0 = __half22float2(*(__half2*)&uqr.x);
    float2 qf1 = __half22float2(*(__half2*)&uqr.y);
    float2 kf0 = __half22float2(*(__half2*)&ukr.x);
    float2 kf1 = __half22float2(*(__half2*)&ukr.y);
    float4 qv = make_float4(qf0.x, qf0.y, qf1.x, qf1.y);
    float4 kv = make_float4(kf0.x, kf0.y, kf1.x, kf1.y);

    float qs  = qv.x + qv.y + qv.z + qv.w;
    float qs2 = qv.x*qv.x + qv.y*qv.y + qv.z*qv.z + qv.w*qv.w;
    float ks  = kv.x + kv.y + kv.z + kv.w;
    float ks2 = kv.x*kv.x + kv.y*kv.y + kv.z*kv.z + kv.w*kv.w;
    #pragma unroll
    for (int o = 16; o >= 1; o >>= 1) {
        qs  += __shfl_xor_sync(0xffffffffu, qs,  o);
        qs2 += __shfl_xor_sync(0xffffffffu, qs2, o);
        ks  += __shfl_xor_sync(0xffffffffu, ks,  o);
        ks2 += __shfl_xor_sync(0xffffffffu, ks2, o);
    }
    __shared__ float red[4][8];
    __shared__ float stat[4];
    int lane = t & 31, wp = t >> 5;
    if (lane == 0) { red[0][wp]=qs; red[1][wp]=qs2; red[2][wp]=ks; red[3][wp]=ks2; }
    __syncthreads();
    if (t == 0) {
        float a=0,c=0,e=0,f=0;
        #pragma unroll
        for (int i=0;i<8;i++){a+=red[0][i];c+=red[1][i];e+=red[2][i];f+=red[3][i];}
        float qmu=a*(1.f/D_), qvr=c*(1.f/D_)-qmu*qmu;
        float kmu=e*(1.f/D_), kvr=f*(1.f/D_)-kmu*kmu;
        stat[0]=qmu; stat[1]=rsqrtf(qvr+EPS);
        stat[2]=kmu; stat[3]=rsqrtf(kvr+EPS);
    }
    __syncthreads();
    float qmu=stat[0], qrs=stat[1], kmu=stat[2], krs=stat[3];
    float4 qwv = *(const float4*)&qw[t*4];
    float4 kwv = *(const float4*)&kw[t*4];
    float qnv[4], knv[4];
    qnv[0]=(qv.x-qmu)*qrs*qwv.x; qnv[1]=(qv.y-qmu)*qrs*qwv.y;
    qnv[2]=(qv.z-qmu)*qrs*qwv.z; qnv[3]=(qv.w-qmu)*qrs*qwv.w;
    knv[0]=(kv.x-kmu)*krs*kwv.x; knv[1]=(kv.y-kmu)*krs*kwv.y;
    knv[2]=(kv.z-kmu)*krs*kwv.z; knv[3]=(kv.w-kmu)*krs*kwv.w;

    // RoPE partner (d +/- 32) lives exactly 8 lanes away in the same warp
    float qp[4], kp[4];
    #pragma unroll
    for (int ii = 0; ii < 4; ii++) {
        qp[ii] = __shfl_xor_sync(0xffffffffu, qnv[ii], 8);
        kp[ii] = __shfl_xor_sync(0xffffffffu, knv[ii], 8);
    }
    bool hiHalf = (t & 8) != 0;     // j0 >= 32
    int d0 = t * 4;
    int hh = d0 >> 6;
    int j0 = d0 & 63;
    int f0 = d0 & 31;
    float qo[4], ko[4];
    #pragma unroll
    for (int ii = 0; ii < 4; ii++) {
        float c = g_cos[l * 32 + f0 + ii];
        float s = g_sin[l * 32 + f0 + ii];
        if (!hiHalf) {
            qo[ii] = qnv[ii] * c - qp[ii] * s;
            ko[ii] = knv[ii] * c - kp[ii] * s;
        } else {
            qo[ii] = qnv[ii] * c + qp[ii] * s;
            ko[ii] = knv[ii] * c + kp[ii] * s;
        }
        qo[ii] *= 0.125f;   // fold softmax scale into q
    }
    size_t oidx = (((size_t)(b * H_ + hh)) * L_ + l) * DH + j0;
    __half2 q01 = __floats2half2_rn(qo[0], qo[1]);
    __half2 q23 = __floats2half2_rn(qo[2], qo[3]);
    __half2 k01 = __floats2half2_rn(ko[0], ko[1]);
    __half2 k23 = __floats2half2_rn(ko[2], ko[3]);
    uint2 uq, uk;
    uq.x = *(uint32_t*)&q01; uq.y = *(uint32_t*)&q23;
    uk.x = *(uint32_t*)&k01; uk.y = *(uint32_t*)&k23;
    *(uint2*)&g_qf[oidx] = uq;
    *(uint2*)&g_kf[oidx] = uk;
}

// ---------------- flash attention on mma.sync (fp16 single-term) ----------------
// Q-tile 128 rows, 8 warps (warp w -> rows w*16..w*16+15). One 64-col K/V tile
// feeds all 128 q-rows. Q staging smem ALIASES KV buffer 1.
#define KPAD 72
#define A5_TILE 9216
#define A5_BUF  18432
#define A5_SK   36864
#define ATT5_SMEM (A5_SK + 512)

__global__ __launch_bounds__(256) void attn_mma(const int* __restrict__ seq_id) {
    extern __shared__ char sm[];
    const uint32_t sbase = smem_u32(sm);
    int tid = threadIdx.x, lane = tid & 31, w = tid >> 5;
    int qt = blockIdx.x, h = blockIdx.y, b = blockIdx.z;
    int bh = b * H_ + h;
    int row0 = qt * 128;

    const __half* gQf = g_qf + ((size_t)bh * L_ + row0) * DH;
    const __half* gKf = g_kf + (size_t)bh * L_ * DH;
    const __half* gVf = g_vtf + (size_t)bh * DH * L_;

    // ---- valid k-tile range (contiguous because seq_id is sorted) ----
    int q_lo = seq_id[b * L_ + row0];
    int q_hi = seq_id[b * L_ + row0 + 127];
    unsigned vmask;
    {
        int klo = seq_id[b * L_ + lane * 64];
        int khi = seq_id[b * L_ + lane * 64 + 63];
        bool ok = (khi >= q_lo) && (klo <= q_hi);
        vmask = __ballot_sync(0xffffffffu, ok);
    }
    int tlo = __ffs(vmask) - 1;
    int thi = 31 - __clz(vmask);

    // ---- prologue: Q tile (128 rows x 8 chunks = 1024 chunks / 256 thr) ----
    {
        int lrow = tid >> 1;           // 0..127
        int cb0  = (tid & 1) * 4;
        #pragma unroll
        for (int c = 0; c < 4; c++) {
            int ch = cb0 + c;
            uint32_t so = (uint32_t)(lrow * KPAD + ch * 8) * 2;
            CP_ASYNC16(sbase + so, gQf + lrow * DH + ch * 8);
        }
    }
    CP_COMMIT();
    // ---- K/V tile tlo into buf0: threads [0,128) load K, [128,256) load V ----
    int kvrow = (tid & 127) >> 1;      // 0..63
    int kvcb  = (tid & 1) * 4;
    bool isV  = tid >= 128;
    {
        int col0 = tlo * 64;
        uint32_t dst = sbase + A5_BUF + (isV ? (uint32_t)A5_TILE : 0u);
        #pragma unroll
        for (int c = 0; c < 4; c++) {
            int ch = kvcb + c;
            uint32_t so = (uint32_t)(kvrow * KPAD + ch * 8) * 2;
            const __half* src = isV ? gVf + (size_t)kvrow * L_ + col0 + ch * 8
                                    : gKf + (size_t)(col0 + kvrow) * DH + ch * 8;
            CP_ASYNC16(dst + so, src);
        }
    }
    CP_COMMIT();
    if (tid < 64) ((int*)(sm + A5_SK))[tid] = seq_id[b * L_ + tlo * 64 + tid];
    int sq0 = seq_id[b * L_ + row0 + w * 16 + (lane >> 2)];
    int sq1 = seq_id[b * L_ + row0 + w * 16 + (lane >> 2) + 8];

    CP_WAIT1();                 // Q group complete (KV0 may be in flight)
    __syncthreads();

    // ---- extract Q fragments (held for whole kernel); frees buf1 region ----
    uint32_t qf[4][4];
    {
        const __half* sQ = (const __half*)sm;
        #pragma unroll
        for (int s = 0; s < 4; s++) {
            int base = (w * 16 + (lane >> 2)) * KPAD + s * 16 + (lane & 3) * 2;
            qf[s][0] = *(const uint32_t*)(sQ + base);
            qf[s][1] = *(const uint32_t*)(sQ + base + 8 * KPAD);
            qf[s][2] = *(const uint32_t*)(sQ + base + 8);
            qf[s][3] = *(const uint32_t*)(sQ + base + 8 * KPAD + 8);
        }
    }

    float m0 = -1e30f, m1 = -1e30f, l0 = 0.f, l1 = 0.f;
    float pv[8][4];
    #pragma unroll
    for (int j = 0; j < 8; j++)
        #pragma unroll
        for (int r = 0; r < 4; r++) pv[j][r] = 0.f;

    for (int it = tlo; it <= thi; it++) {
        int buf = (it - tlo) & 1;               // 0 -> region A5_BUF, 1 -> region 0
        uint32_t kvb  = sbase + (buf ? 0u : (uint32_t)A5_BUF);
        uint32_t kvbn = sbase + (buf ? (uint32_t)A5_BUF : 0u);
        CP_WAIT0();
        __syncthreads();                         // Q frags extracted by all warps

        // prefetch next tile into the other region (overwrites Q on first iter)
        if (it + 1 <= thi) {
            int col0n = (it + 1) * 64;
            uint32_t dst = kvbn + (isV ? (uint32_t)A5_TILE : 0u);
            #pragma unroll
            for (int c = 0; c < 4; c++) {
                int ch = kvcb + c;
                uint32_t so = (uint32_t)(kvrow * KPAD + ch * 8) * 2;
                const __half* src = isV ? gVf + (size_t)kvrow * L_ + col0n + ch * 8
                                        : gKf + (size_t)(col0n + kvrow) * DH + ch * 8;
                CP_ASYNC16(dst + so, src);
            }
            if (tid < 64)
                ((int*)(sm + A5_SK))[(buf ^ 1) * 64 + tid] =
                    seq_id[b * L_ + col0n + tid];
        }
        CP_COMMIT();

        const __half* sK = (const __half*)(sm + (kvb - sbase));
        const __half* sV = sK + A5_TILE / 2;
        const int* skp = (const int*)(sm + A5_SK) + buf * 64;

        // ---- S = Q K^T (fp16 single) ----
        float sf[8][4];
        #pragma unroll
        for (int j = 0; j < 8; j++)
            #pragma unroll
            for (int r = 0; r < 4; r++) sf[j][r] = 0.f;
        #pragma unroll
        for (int s = 0; s < 4; s++) {
            #pragma unroll
            for (int j = 0; j < 8; j++) {
                int off = (j * 8 + (lane >> 2)) * KPAD + s * 16 + (lane & 3) * 2;
                uint32_t bf[2] = {*(const uint32_t*)(sK + off),
                                  *(const uint32_t*)(sK + off + 8)};
                MMAF16(sf[j], qf[s], bf);
            }
        }

        // ---- mask + online softmax (c-frag layout) ----
        int colb = (lane & 3) * 2;
        float nm0 = m0, nm1 = m1;
        #pragma unroll
        for (int j = 0; j < 8; j++) {
            int k0 = skp[8 * j + colb], k1 = skp[8 * j + colb + 1];
            sf[j][0] = (k0 == sq0) ? sf[j][0] : -2e30f;
            sf[j][1] = (k1 == sq0) ? sf[j][1] : -2e30f;
            sf[j][2] = (k0 == sq1) ? sf[j][2] : -2e30f;
            sf[j][3] = (k1 == sq1) ? sf[j][3] : -2e30f;
            nm0 = fmaxf(nm0, fmaxf(sf[j][0], sf[j][1]));
            nm1 = fmaxf(nm1, fmaxf(sf[j][2], sf[j][3]));
        }
        nm0 = fmaxf(nm0, __shfl_xor_sync(0xffffffffu, nm0, 1));
        nm0 = fmaxf(nm0, __shfl_xor_sync(0xffffffffu, nm0, 2));
        nm1 = fmaxf(nm1, __shfl_xor_sync(0xffffffffu, nm1, 1));
        nm1 = fmaxf(nm1, __shfl_xor_sync(0xffffffffu, nm1, 2));
        float a0 = __expf(m0 - nm0), a1 = __expf(m1 - nm1);
        m0 = nm0; m1 = nm1;

        float s0 = 0.f, s1 = 0.f;
        uint32_t ph[4][4];
        #pragma unroll
        for (int j = 0; j < 8; j++) {
            float p0 = __expf(sf[j][0] - m0), p1 = __expf(sf[j][1] - m0);
            float p2 = __expf(sf[j][2] - m1), p3 = __expf(sf[j][3] - m1);
            s0 += p0 + p1; s1 += p2 + p3;
            __half2 h01 = __floats2half2_rn(p0, p1);
            __half2 h23 = __floats2half2_rn(p2, p3);
            int s_ = j >> 1;
            int o  = (j & 1) * 2;
            ph[s_][o]     = *(uint32_t*)&h01;
            ph[s_][o + 1] = *(uint32_t*)&h23;
        }
        s0 += __shfl_xor_sync(0xffffffffu, s0, 1);
        s0 += __shfl_xor_sync(0xffffffffu, s0, 2);
        s1 += __shfl_xor_sync(0xffffffffu, s1, 1);
        s1 += __shfl_xor_sync(0xffffffffu, s1, 2);
        l0 = l0 * a0 + s0;
        l1 = l1 * a1 + s1;
        #pragma unroll
        for (int j = 0; j < 8; j++) {
            pv[j][0] *= a0; pv[j][1] *= a0; pv[j][2] *= a1; pv[j][3] *= a1;
        }

        // ---- PV (fp16 single), B = Vt[dh][c] ----
        #pragma unroll
        for (int s = 0; s < 4; s++) {
            #pragma unroll
            for (int j = 0; j < 8; j++) {
                int off = (j * 8 + (lane >> 2)) * KPAD + s * 16 + (lane & 3) * 2;
                uint32_t bf[2] = {*(const uint32_t*)(sV + off),
                                  *(const uint32_t*)(sV + off + 8)};
                MMAF16(pv[j], ph[s], bf);
            }
        }
    }

    // ---- epilogue: ctx / l -> fp16 [B,L,H,DH] ----
    float inv0 = 1.0f / l0, inv1 = 1.0f / l1;
    int r0g = row0 + w * 16 + (lane >> 2);
    #pragma unroll
    for (int j = 0; j < 8; j++) {
        int c = 8 * j + (lane & 3) * 2;
        size_t o0 = (((size_t)b * L_ + r0g) * H_ + h) * DH + c;
        size_t o1 = (((size_t)b * L_ + r0g + 8) * H_ + h) * DH + c;
        __half2 hx = __floats2half2_rn(pv[j][0] * inv0, pv[j][1] * inv0);
        __half2 hy = __floats2half2_rn(pv[j][2] * inv1, pv[j][3] * inv1);
        *(uint32_t*)&g_cf[o0] = *(uint32_t*)&hx;
        *(uint32_t*)&g_cf[o1] = *(uint32_t*)&hy;
    }
}

// ---------------- launch ----------------
extern "C" void kernel_launch(void* const* d_in, const int* in_sizes, int n_in,
                              void* d_out, int out_size) {
    const float* x      = (const float*)d_in[0];
    const int*   seq_id = (const int*)  d_in[1];
    const float* ln1_w  = (const float*)d_in[2];
    const float* ln1_b  = (const float*)d_in[3];
    const float* w_qkv  = (const float*)d_in[4];
    const float* q_ln_w = (const float*)d_in[5];
    const float* k_ln_w = (const float*)d_in[6];
    const float* out_w  = (const float*)d_in[7];
    float* out = (float*)d_out;

    void *phf, *pwqf, *powf, *pcf, *pqkvh;
    cudaGetSymbolAddress(&phf,   g_hf);
    cudaGetSymbolAddress(&pwqf,  g_wqf);
    cudaGetSymbolAddress(&powf,  g_owf);
    cudaGetSymbolAddress(&pcf,   g_cf);
    cudaGetSymbolAddress(&pqkvh, g_qkvh);

    cudaFuncSetAttribute(attn_mma, cudaFuncAttributeMaxDynamicSharedMemorySize,
                         ATT5_SMEM);
    cudaFuncSetAttribute(gemm_f16, cudaFuncAttributeMaxDynamicSharedMemorySize,
                         GEMM_SMEM_BYTES);

    prep_kernel<<<8448, 256>>>(x, ln1_w, ln1_b, w_qkv, out_w);
    gemm_f16<<<dim3(D3 / 128, NT / 128), 256, GEMM_SMEM_BYTES>>>(
        (const __half*)phf, (const __half*)pwqf, pqkvh, NT, D3, D_, 1);
    qkrope_vt_kernel<<<6144, 256>>>(q_ln_w, k_ln_w);
    attn_mma<<<dim3(L_ / 128, H_, B_), 256, ATT5_SMEM>>>(seq_id);
    gemm_f16<<<dim3(D_ / 128, NT / 128), 256, GEMM_SMEM_BYTES>>>(
        (const __half*)pcf, (const __half*)powf, out, NT, D_, D_, 0);
}